// round 14
// baseline (speedup 1.0000x reference)
#include <cuda_runtime.h>

// ---------------------------------------------------------------------------
// TorchFovea R13: R12 + 4-wide pyrdown hpass, float2 epilogue loads in
// recon01, vectorized hb3/dn3 in fused_mid. 5 launches.
// ---------------------------------------------------------------------------

#define NPL 96

#define H0 360
#define W0 640
#define H1 180
#define W1 320
#define H2 90
#define W2 160
#define H3 45
#define W3 80
#define H4 23
#define W4 40
#define H5 12
#define W5 20

#define ROWV_TOT (1279 + 640 + 320 + 160 + 80)
#define COLV_TOT (719 + 360 + 180 + 90 + 45)
#define RO0 0
#define RO1 1279
#define RO2 1919
#define RO3 2239
#define RO4 2399
#define CO0 0
#define CO1 719
#define CO2 1079
#define CO3 1259
#define CO4 1349

__device__ float g_rowv[ROWV_TOT];
__device__ float g_colv[COLV_TOT];
__device__ float g_dn1[NPL * H1 * W1];
__device__ float g_dn2[NPL * H2 * W2];
__device__ float g_F2[NPL * H2 * W2];

__device__ __forceinline__ int refl(int i, int n) {
    i = (i < 0) ? -i : i;
    return (i >= n) ? (2 * n - 2 - i) : i;
}

// ---------------------------------------------------------------------------
__device__ __forceinline__ float pd1_at(const float* __restrict__ v, int N, int o) {
    int x = 2 * o;
    return 0.375f * v[x]
         + 0.25f  * (v[refl(x - 1, N)] + v[refl(x + 1, N)])
         + 0.0625f * (v[refl(x - 2, N)] + v[refl(x + 2, N)]);
}

__global__ void gen_filters_kernel(float* __restrict__ rowv, float* __restrict__ colv) {
    const int t = threadIdx.x;
    const int NT = blockDim.x;
    for (int i = t; i < 1279; i += NT) {
        float d = (float)(i - 640);
        rowv[RO0 + i] = expf(-d * d / 10082.0f);
    }
    for (int j = t; j < 719; j += NT) {
        float d = (float)(j - 360);
        colv[CO0 + j] = expf(-d * d / 10082.0f);
    }
    __syncthreads();
    const int rN[5] = {1279, 640, 320, 160, 80};
    const int rO[5] = {RO0, RO1, RO2, RO3, RO4};
    const int cN[5] = {719, 360, 180, 90, 45};
    const int cO[5] = {CO0, CO1, CO2, CO3, CO4};
#pragma unroll
    for (int k = 1; k < 5; k++) {
        const float* ri = rowv + rO[k - 1];
        float* ro = rowv + rO[k];
        for (int o = t; o < rN[k]; o += NT) ro[o] = pd1_at(ri, rN[k - 1], o);
        const float* ci = colv + cO[k - 1];
        float* co = colv + cO[k];
        for (int o = t; o < cN[k]; o += NT) co[o] = pd1_at(ci, cN[k - 1], o);
        __syncthreads();
    }
}

// ---------------------------------------------------------------------------
// pyrDown: block (16,16) -> 32x16 output tile. 4-wide hpass.
// ---------------------------------------------------------------------------
#define PTX 32
#define PTY 16
#define PIW (2 * PTX + 4)   // 68
#define PIH (2 * PTY + 4)   // 36

__global__ void __launch_bounds__(256) pyrdown_st(
        const float* __restrict__ src, float* __restrict__ dst,
        int H, int W, int oH, int oW) {
    int c = blockIdx.z;
    const float* s = src + (size_t)c * H * W;
    float* d = dst + (size_t)c * oH * oW;
    int ox0 = blockIdx.x * PTX;
    int oy0 = blockIdx.y * PTY;

    __shared__ float in[PIH][PIW];
    __shared__ float hb[PIH][PTX];

    int tid = threadIdx.y * 16 + threadIdx.x;

    bool interior = (ox0 >= 1) && (2 * ox0 + 65 <= W - 1)
                 && (oy0 >= 1) && (2 * oy0 + 33 <= H - 1);

    if (interior) {
        const float2* s2 = (const float2*)(s + (size_t)(2 * oy0 - 2) * W + (2 * ox0 - 2));
        const int stride2 = W >> 1;
        for (int idx = tid; idx < PIH * (PIW / 2); idx += 256) {
            int r = idx / (PIW / 2);
            int j = idx - r * (PIW / 2);
            *(float2*)&in[r][2 * j] = s2[r * stride2 + j];
        }
    } else {
        for (int idx = tid; idx < PIH * PIW; idx += 256) {
            int r = idx / PIW;
            int col = idx - r * PIW;
            int gy = refl(2 * oy0 - 2 + r, H);
            int gx = refl(2 * ox0 - 2 + col, W);
            in[r][col] = s[(size_t)gy * W + gx];
        }
    }
    __syncthreads();

    const float k0 = 0.0625f, k1 = 0.25f, k2 = 0.375f;
    // horizontal pass: 4 outputs per iteration (288 iters over 256 threads)
    for (int idx = tid; idx < PIH * (PTX / 4); idx += 256) {
        int r = idx >> 3;
        int jj = idx & 7;
        const float* row = in[r] + 8 * jj;
        float2 a  = *(const float2*)(row);
        float2 bb = *(const float2*)(row + 2);
        float2 cc = *(const float2*)(row + 4);
        float2 dd = *(const float2*)(row + 6);
        float2 ee = *(const float2*)(row + 8);
        float  gg = row[10];
        float4 h;
        h.x = k0 * (a.x + cc.x)  + k1 * (a.y + bb.y)  + k2 * bb.x;
        h.y = k0 * (bb.x + dd.x) + k1 * (bb.y + cc.y) + k2 * cc.x;
        h.z = k0 * (cc.x + ee.x) + k1 * (cc.y + dd.y) + k2 * dd.x;
        h.w = k0 * (dd.x + gg)   + k1 * (dd.y + ee.y) + k2 * ee.x;
        *(float4*)&hb[r][4 * jj] = h;
    }
    __syncthreads();

    int oy = oy0 + threadIdx.y;
    int ox = ox0 + 2 * threadIdx.x;
    if (oy < oH && ox < oW) {
        int r = 2 * threadIdx.y;
        int j = 2 * threadIdx.x;
        float2 h0 = *(const float2*)&hb[r][j];
        float2 h1 = *(const float2*)&hb[r + 1][j];
        float2 h2 = *(const float2*)&hb[r + 2][j];
        float2 h3 = *(const float2*)&hb[r + 3][j];
        float2 h4 = *(const float2*)&hb[r + 4][j];
        float2 o;
        o.x = k0 * (h0.x + h4.x) + k1 * (h1.x + h3.x) + k2 * h2.x;
        o.y = k0 * (h0.y + h4.y) + k1 * (h1.y + h3.y) + k2 * h2.y;
        *(float2*)(d + (size_t)oy * oW + ox) = o;
    }
}

// ---------------------------------------------------------------------------
__device__ __forceinline__ float pd2_at(const float* __restrict__ s, int H, int W,
                                        int y, int x) {
    int ry[5], rx[5];
#pragma unroll
    for (int i = 0; i < 5; i++) {
        ry[i] = refl(2 * y - 2 + i, H);
        rx[i] = refl(2 * x - 2 + i, W);
    }
    const float k0 = 0.0625f, k1 = 0.25f, k2 = 0.375f;
    float acc = 0.0f;
#pragma unroll
    for (int i = 0; i < 5; i++) {
        const float* row = s + ry[i] * W;
        float r = k2 * row[rx[2]]
                + k1 * (row[rx[1]] + row[rx[3]])
                + k0 * (row[rx[0]] + row[rx[4]]);
        float kw = (i == 2) ? k2 : ((i == 1 || i == 3) ? k1 : k0);
        acc += kw * r;
    }
    return acc;
}

__device__ __forceinline__ void pyrup_quad(const float* __restrict__ s, int H, int W,
                                           int qy, int qx,
                                           float& ee, float& eo, float& oe, float& oo) {
    int xl = (qx == 0) ? 1 : qx - 1;
    int xr = (qx < W - 1) ? qx + 1 : W - 1;
    int yu = (qy == 0) ? 1 : qy - 1;
    int yd = (qy < H - 1) ? qy + 1 : H - 1;
    const float* r0 = s + yu * W;
    const float* r1 = s + qy * W;
    const float* r2 = s + yd * W;
    float a00 = r0[xl], a01 = r0[qx], a02 = r0[xr];
    float a10 = r1[xl], a11 = r1[qx], a12 = r1[xr];
    float a20 = r2[xl], a21 = r2[qx], a22 = r2[xr];
    float he0 = 0.125f * (a00 + a02) + 0.75f * a01;
    float he1 = 0.125f * (a10 + a12) + 0.75f * a11;
    float he2 = 0.125f * (a20 + a22) + 0.75f * a21;
    float ho0 = 0.5f * (a01 + a02);
    float ho1 = 0.5f * (a11 + a12);
    float ho2 = 0.5f * (a21 + a22);
    ee = 0.125f * (he0 + he2) + 0.75f * he1;
    eo = 0.125f * (ho0 + ho2) + 0.75f * ho1;
    oe = 0.5f * (he1 + he2);
    oo = 0.5f * (ho1 + ho2);
}

// ---------------------------------------------------------------------------
// Fused mid levels: vectorized hb3 (3 loads) and paired-column dn3.
// ---------------------------------------------------------------------------
#define FNT 1024
#define SM_DN2 0
#define SM_HB3 14400
#define SM_DN3 21600
#define SM_DN4 25200
#define SM_DN5 26120
#define SM_F4  26360
#define SM_TOT 27280

__global__ void __launch_bounds__(FNT) fused_mid_kernel(
        const float* __restrict__ dn2,
        const float* __restrict__ colv, const float* __restrict__ rowv,
        const float* __restrict__ fixations,
        float* __restrict__ F2g) {
    extern __shared__ float sm[];
    float* s_dn2 = sm + SM_DN2;
    float* s_hb3 = sm + SM_HB3;
    float* s_F3  = sm + SM_HB3;
    float* s_dn3 = sm + SM_DN3;
    float* s_dn4 = sm + SM_DN4;
    float* s_dn5 = sm + SM_DN5;
    float* s_F4  = sm + SM_F4;

    const int p = blockIdx.x;
    const int b = p / 3;
    const int t = threadIdx.x;
    const float k0 = 0.0625f, k1 = 0.25f, k2 = 0.375f;

    const float4* src4 = (const float4*)(dn2 + (size_t)p * (H2 * W2));
    for (int i = t; i < (H2 * W2) / 4; i += FNT) ((float4*)s_dn2)[i] = src4[i];
    __syncthreads();

    // hb3 (90 x 80)
    for (int idx = t; idx < H2 * W3; idx += FNT) {
        int y = idx / W3;
        int ox = idx - y * W3;
        const float* row = s_dn2 + y * W2;
        int xc = 2 * ox;
        float v;
        if (ox >= 1 && ox <= W3 - 2) {
            float2 m = *(const float2*)(row + xc - 2);
            float2 n = *(const float2*)(row + xc);
            v = k0 * (m.x + row[xc + 2]) + k1 * (m.y + n.y) + k2 * n.x;
        } else {
            v = k2 * row[xc]
              + k1 * (row[refl(xc - 1, W2)] + row[refl(xc + 1, W2)])
              + k0 * (row[refl(xc - 2, W2)] + row[refl(xc + 2, W2)]);
        }
        s_hb3[idx] = v;
    }
    __syncthreads();

    // dn3 (45 x 80): paired columns, float2 loads/stores
    for (int idx = t; idx < H3 * (W3 / 2); idx += FNT) {
        int oy = idx / (W3 / 2);
        int oxp = idx - oy * (W3 / 2);
        int yc = 2 * oy;
        int r0, r1, r3, r4;
        if (oy >= 1 && oy <= H3 - 2) {
            r0 = yc - 2; r1 = yc - 1; r3 = yc + 1; r4 = yc + 2;
        } else {
            r0 = refl(yc - 2, H2); r1 = refl(yc - 1, H2);
            r3 = refl(yc + 1, H2); r4 = refl(yc + 2, H2);
        }
        int col = 2 * oxp;
        float2 h0 = *(const float2*)&s_hb3[r0 * W3 + col];
        float2 h1 = *(const float2*)&s_hb3[r1 * W3 + col];
        float2 h2 = *(const float2*)&s_hb3[yc * W3 + col];
        float2 h3 = *(const float2*)&s_hb3[r3 * W3 + col];
        float2 h4 = *(const float2*)&s_hb3[r4 * W3 + col];
        float2 v;
        v.x = k0 * (h0.x + h4.x) + k1 * (h1.x + h3.x) + k2 * h2.x;
        v.y = k0 * (h0.y + h4.y) + k1 * (h1.y + h3.y) + k2 * h2.y;
        *(float2*)&s_dn3[oy * W3 + col] = v;
    }
    __syncthreads();

    for (int idx = t; idx < H4 * W4; idx += FNT)
        s_dn4[idx] = pd2_at(s_dn3, H3, W3, idx / W4, idx % W4);
    __syncthreads();
    for (int idx = t; idx < H5 * W5; idx += FNT)
        s_dn5[idx] = pd2_at(s_dn4, H4, W4, idx / W5, idx % W5);
    __syncthreads();

    const float fxx = fixations[2 * b];
    const float fyy = fixations[2 * b + 1];

    {   // level 4
        int x1 = min(max((int)(40.0f - fxx * 0.0625f), 0), W3 - W4);
        int y1 = min(max((int)(22.5f - fyy * 0.0625f), 0), H3 - H4);
        const float* cv = colv + CO4 + y1;
        const float* rv = rowv + RO4 + x1;
        const int qH = (H4 + 1) / 2, qW = W4 / 2;
        for (int idx = t; idx < qH * qW; idx += FNT) {
            int qy = idx / qW;
            int qx = idx - qy * qW;
            float ee, eo, oe, oo;
            pyrup_quad(s_dn5, H5, W5, qy, qx, ee, eo, oe, oo);
            int y0 = 2 * qy, x0 = 2 * qx;
            float rw0 = rv[x0], rw1 = rv[x0 + 1];
            float cw0 = cv[y0];
            s_F4[y0 * W4 + x0]     = ee + (s_dn4[y0 * W4 + x0]     - ee) * (cw0 * rw0);
            s_F4[y0 * W4 + x0 + 1] = eo + (s_dn4[y0 * W4 + x0 + 1] - eo) * (cw0 * rw1);
            if (y0 + 1 < H4) {
                float cw1 = cv[y0 + 1];
                s_F4[(y0 + 1) * W4 + x0]     = oe + (s_dn4[(y0 + 1) * W4 + x0]     - oe) * (cw1 * rw0);
                s_F4[(y0 + 1) * W4 + x0 + 1] = oo + (s_dn4[(y0 + 1) * W4 + x0 + 1] - oo) * (cw1 * rw1);
            }
        }
    }
    __syncthreads();

    {   // level 3
        int x1 = min(max((int)(80.0f - fxx * 0.125f), 0), W2 - W3);
        int y1 = min(max((int)(45.0f - fyy * 0.125f), 0), H2 - H3);
        const float* cv = colv + CO3 + y1;
        const float* rv = rowv + RO3 + x1;
        const int qH = (H3 + 1) / 2, qW = W3 / 2;
        for (int idx = t; idx < qH * qW; idx += FNT) {
            int qy = idx / qW;
            int qx = idx - qy * qW;
            float Fee, Feo, Foe, Foo, Dee, Deo, Doe, Doo;
            pyrup_quad(s_F4, H4, W4, qy, qx, Fee, Feo, Foe, Foo);
            pyrup_quad(s_dn4, H4, W4, qy, qx, Dee, Deo, Doe, Doo);
            int y0 = 2 * qy, x0 = 2 * qx;
            float rw0 = rv[x0], rw1 = rv[x0 + 1];
            float cw0 = cv[y0];
            s_F3[y0 * W3 + x0]     = Fee + (s_dn3[y0 * W3 + x0]     - Dee) * (cw0 * rw0);
            s_F3[y0 * W3 + x0 + 1] = Feo + (s_dn3[y0 * W3 + x0 + 1] - Deo) * (cw0 * rw1);
            if (y0 + 1 < H3) {
                float cw1 = cv[y0 + 1];
                s_F3[(y0 + 1) * W3 + x0]     = Foe + (s_dn3[(y0 + 1) * W3 + x0]     - Doe) * (cw1 * rw0);
                s_F3[(y0 + 1) * W3 + x0 + 1] = Foo + (s_dn3[(y0 + 1) * W3 + x0 + 1] - Doo) * (cw1 * rw1);
            }
        }
    }
    __syncthreads();

    {   // level 2 -> global F2
        int x1 = min(max((int)(160.0f - fxx * 0.25f), 0), W1 - W2);
        int y1 = min(max((int)(90.0f - fyy * 0.25f), 0), H1 - H2);
        const float* cv = colv + CO2 + y1;
        const float* rv = rowv + RO2 + x1;
        float* g = F2g + (size_t)p * (H2 * W2);
        const int qH = H2 / 2, qW = W2 / 2;
        for (int idx = t; idx < qH * qW; idx += FNT) {
            int qy = idx / qW;
            int qx = idx - qy * qW;
            float Fee, Feo, Foe, Foo, Dee, Deo, Doe, Doo;
            pyrup_quad(s_F3, H3, W3, qy, qx, Fee, Feo, Foe, Foo);
            pyrup_quad(s_dn3, H3, W3, qy, qx, Dee, Deo, Doe, Doo);
            int y0 = 2 * qy, x0 = 2 * qx;
            float rw0 = rv[x0], rw1 = rv[x0 + 1];
            float cw0 = cv[y0], cw1 = cv[y0 + 1];
            float2 o0, o1;
            o0.x = Fee + (s_dn2[y0 * W2 + x0]     - Dee) * (cw0 * rw0);
            o0.y = Feo + (s_dn2[y0 * W2 + x0 + 1] - Deo) * (cw0 * rw1);
            o1.x = Foe + (s_dn2[(y0 + 1) * W2 + x0]     - Doe) * (cw1 * rw0);
            o1.y = Foo + (s_dn2[(y0 + 1) * W2 + x0 + 1] - Doo) * (cw1 * rw1);
            *(float2*)(g + y0 * W2 + x0) = o0;
            *(float2*)(g + (y0 + 1) * W2 + x0) = o1;
        }
    }
}

// ---------------------------------------------------------------------------
// recon01 with interior fast path; epilogue uses float2 center loads.
// Block (16,16) -> 64x32 output pixels.
// ---------------------------------------------------------------------------
#define RQX 32
#define RQY 16

__global__ void __launch_bounds__(256) recon01(
        const float* __restrict__ F2,
        const float* __restrict__ dn2,
        const float* __restrict__ dn1,
        const float* __restrict__ images,
        const float* __restrict__ colv,
        const float* __restrict__ rowv,
        const float* __restrict__ fixations,
        float* __restrict__ out) {
    __shared__ float sD1[20][36];
    __shared__ float sF1[20][36];
    __shared__ float sF2[12][20];
    __shared__ float sD2[12][20];

    const int p = blockIdx.z;
    const int b = p / 3;
    const int qx0 = blockIdx.x * RQX;
    const int qy0 = blockIdx.y * RQY;
    const int tid = threadIdx.y * 16 + threadIdx.x;

    const float fxx = fixations[2 * b];
    const float fyy = fixations[2 * b + 1];
    const int x1_0 = min(max((int)(639.5f - fxx), 0), 1279 - W0);
    const int y1_0 = min(max((int)(359.5f - fyy), 0), 719 - H0);
    const int x1_1 = min(max((int)(320.0f - fxx * 0.5f), 0), W0 - W1);
    const int y1_1 = min(max((int)(180.0f - fyy * 0.5f), 0), H0 - H1);

    const int base1y = qy0 - 2, base1x = qx0 - 2;
    const int base2y = (qy0 >> 1) - 2, base2x = (qx0 >> 1) - 2;

    const bool interior = (qx0 >= 2) && (qx0 + 34 <= W1) && (qx0 / 2 + 18 <= W2)
                       && (qy0 >= 2) && (qy0 + 18 <= H1) && (qy0 / 2 + 10 <= H2);

    // ---- stage ---------------------------------------------------------------
    if (interior) {
        const float2* p1 = (const float2*)(dn1 + (size_t)p * (H1 * W1)
                                           + (size_t)base1y * W1 + base1x);
        const int st1 = W1 >> 1;
        for (int i = tid; i < 20 * 18; i += 256) {
            int r = i / 18;
            int j = i - r * 18;
            *(float2*)&sD1[r][2 * j] = p1[r * st1 + j];
        }
        const size_t off2 = (size_t)p * (H2 * W2) + (size_t)base2y * W2 + base2x;
        const float2* pf = (const float2*)(F2 + off2);
        const float2* pd = (const float2*)(dn2 + off2);
        const int st2 = W2 >> 1;
        for (int i = tid; i < 12 * 10; i += 256) {
            int r = i / 10;
            int j = i - r * 10;
            *(float2*)&sF2[r][2 * j] = pf[r * st2 + j];
            *(float2*)&sD2[r][2 * j] = pd[r * st2 + j];
        }
    } else {
        const float* s1 = dn1 + (size_t)p * (H1 * W1);
        for (int i = tid; i < 20 * 36; i += 256) {
            int r = i / 36;
            int c = i - r * 36;
            int gr = min(max(base1y + r, 0), H1 - 1);
            int gc = min(max(base1x + c, 0), W1 - 1);
            sD1[r][c] = s1[(size_t)gr * W1 + gc];
        }
        const float* sf = F2 + (size_t)p * (H2 * W2);
        const float* sd = dn2 + (size_t)p * (H2 * W2);
        for (int i = tid; i < 12 * 20; i += 256) {
            int r = i / 20;
            int c = i - r * 20;
            int gr = min(max(base2y + r, 0), H2 - 1);
            int gc = min(max(base2x + c, 0), W2 - 1);
            size_t off = (size_t)gr * W2 + gc;
            sF2[r][c] = sf[off];
            sD2[r][c] = sd[off];
        }
    }
    __syncthreads();

    // ---- F1 tile: 10x18 quads ------------------------------------------------
    {
        const float* cv1 = colv + CO1 + y1_1;
        const float* rv1 = rowv + RO1 + x1_1;
        const int Qy0 = (qy0 >> 1) - 1;
        const int Qx0 = (qx0 >> 1) - 1;
        if (interior) {
            for (int i = tid; i < 10 * 18; i += 256) {
                int qr = i / 18;
                int qc = i - qr * 18;
                float Fee, Feo, Foe, Foo, Dee, Deo, Doe, Doo;
                {
                    float a00 = sF2[qr][qc],     a01 = sF2[qr][qc + 1],     a02 = sF2[qr][qc + 2];
                    float a10 = sF2[qr + 1][qc], a11 = sF2[qr + 1][qc + 1], a12 = sF2[qr + 1][qc + 2];
                    float a20 = sF2[qr + 2][qc], a21 = sF2[qr + 2][qc + 1], a22 = sF2[qr + 2][qc + 2];
                    float he0 = 0.125f * (a00 + a02) + 0.75f * a01;
                    float he1 = 0.125f * (a10 + a12) + 0.75f * a11;
                    float he2 = 0.125f * (a20 + a22) + 0.75f * a21;
                    float ho0 = 0.5f * (a01 + a02);
                    float ho1 = 0.5f * (a11 + a12);
                    float ho2 = 0.5f * (a21 + a22);
                    Fee = 0.125f * (he0 + he2) + 0.75f * he1;
                    Feo = 0.125f * (ho0 + ho2) + 0.75f * ho1;
                    Foe = 0.5f * (he1 + he2);
                    Foo = 0.5f * (ho1 + ho2);
                }
                {
                    float a00 = sD2[qr][qc],     a01 = sD2[qr][qc + 1],     a02 = sD2[qr][qc + 2];
                    float a10 = sD2[qr + 1][qc], a11 = sD2[qr + 1][qc + 1], a12 = sD2[qr + 1][qc + 2];
                    float a20 = sD2[qr + 2][qc], a21 = sD2[qr + 2][qc + 1], a22 = sD2[qr + 2][qc + 2];
                    float he0 = 0.125f * (a00 + a02) + 0.75f * a01;
                    float he1 = 0.125f * (a10 + a12) + 0.75f * a11;
                    float he2 = 0.125f * (a20 + a22) + 0.75f * a21;
                    float ho0 = 0.5f * (a01 + a02);
                    float ho1 = 0.5f * (a11 + a12);
                    float ho2 = 0.5f * (a21 + a22);
                    Dee = 0.125f * (he0 + he2) + 0.75f * he1;
                    Deo = 0.125f * (ho0 + ho2) + 0.75f * ho1;
                    Doe = 0.5f * (he1 + he2);
                    Doo = 0.5f * (ho1 + ho2);
                }
                int gy = 2 * (Qy0 + qr), gx = 2 * (Qx0 + qc);
                int r0 = 2 * qr;
                int c0 = 2 * qc;
                float cw0 = cv1[gy], cw1 = cv1[gy + 1];
                float rw0 = rv1[gx], rw1 = rv1[gx + 1];
                float2 d0 = *(const float2*)&sD1[r0][c0];
                float2 d1 = *(const float2*)&sD1[r0 + 1][c0];
                float2 f0, f1;
                f0.x = Fee + (d0.x - Dee) * (cw0 * rw0);
                f0.y = Feo + (d0.y - Deo) * (cw0 * rw1);
                f1.x = Foe + (d1.x - Doe) * (cw1 * rw0);
                f1.y = Foo + (d1.y - Doo) * (cw1 * rw1);
                *(float2*)&sF1[r0][c0]     = f0;
                *(float2*)&sF1[r0 + 1][c0] = f1;
            }
        } else {
            for (int i = tid; i < 10 * 18; i += 256) {
                int qr = i / 18;
                int qc = i - qr * 18;
                int Qy = Qy0 + qr;
                int Qx = Qx0 + qc;
                if (Qy < 0 || Qy >= H2 || Qx < 0 || Qx >= W2) continue;

                int yu = ((Qy == 0) ? 1 : Qy - 1) - base2y;
                int yc = Qy - base2y;
                int yd = ((Qy < H2 - 1) ? Qy + 1 : H2 - 1) - base2y;
                int xl = ((Qx == 0) ? 1 : Qx - 1) - base2x;
                int xc = Qx - base2x;
                int xr = ((Qx < W2 - 1) ? Qx + 1 : W2 - 1) - base2x;

                float Fee, Feo, Foe, Foo, Dee, Deo, Doe, Doo;
                {
                    float a00 = sF2[yu][xl], a01 = sF2[yu][xc], a02 = sF2[yu][xr];
                    float a10 = sF2[yc][xl], a11 = sF2[yc][xc], a12 = sF2[yc][xr];
                    float a20 = sF2[yd][xl], a21 = sF2[yd][xc], a22 = sF2[yd][xr];
                    float he0 = 0.125f * (a00 + a02) + 0.75f * a01;
                    float he1 = 0.125f * (a10 + a12) + 0.75f * a11;
                    float he2 = 0.125f * (a20 + a22) + 0.75f * a21;
                    float ho0 = 0.5f * (a01 + a02);
                    float ho1 = 0.5f * (a11 + a12);
                    float ho2 = 0.5f * (a21 + a22);
                    Fee = 0.125f * (he0 + he2) + 0.75f * he1;
                    Feo = 0.125f * (ho0 + ho2) + 0.75f * ho1;
                    Foe = 0.5f * (he1 + he2);
                    Foo = 0.5f * (ho1 + ho2);
                }
                {
                    float a00 = sD2[yu][xl], a01 = sD2[yu][xc], a02 = sD2[yu][xr];
                    float a10 = sD2[yc][xl], a11 = sD2[yc][xc], a12 = sD2[yc][xr];
                    float a20 = sD2[yd][xl], a21 = sD2[yd][xc], a22 = sD2[yd][xr];
                    float he0 = 0.125f * (a00 + a02) + 0.75f * a01;
                    float he1 = 0.125f * (a10 + a12) + 0.75f * a11;
                    float he2 = 0.125f * (a20 + a22) + 0.75f * a21;
                    float ho0 = 0.5f * (a01 + a02);
                    float ho1 = 0.5f * (a11 + a12);
                    float ho2 = 0.5f * (a21 + a22);
                    Dee = 0.125f * (he0 + he2) + 0.75f * he1;
                    Deo = 0.125f * (ho0 + ho2) + 0.75f * ho1;
                    Doe = 0.5f * (he1 + he2);
                    Doo = 0.5f * (ho1 + ho2);
                }

                int gy = 2 * Qy, gx = 2 * Qx;
                int r0 = gy - base1y;
                int c0 = gx - base1x;
                float cw0 = cv1[gy], cw1 = cv1[gy + 1];
                float rw0 = rv1[gx], rw1 = rv1[gx + 1];
                sF1[r0][c0]         = Fee + (sD1[r0][c0]         - Dee) * (cw0 * rw0);
                sF1[r0][c0 + 1]     = Feo + (sD1[r0][c0 + 1]     - Deo) * (cw0 * rw1);
                sF1[r0 + 1][c0]     = Foe + (sD1[r0 + 1][c0]     - Doe) * (cw1 * rw0);
                sF1[r0 + 1][c0 + 1] = Foo + (sD1[r0 + 1][c0 + 1] - Doo) * (cw1 * rw1);
            }
        }
    }
    __syncthreads();

    // ---- level-0 recon: two quads per thread, float4 rows -------------------
    const int ty = threadIdx.y;
    const int qy = qy0 + ty;
    if (qy >= H1) return;
    const int qxA = qx0 + 2 * threadIdx.x;

    const int cb = 2 * threadIdx.x + 2;
    int la, rb, ru, rd;
    if (interior) {
        la = cb - 1;
        rb = cb + 2;
        ru = ty + 1;
        rd = ty + 3;
    } else {
        la = (qxA == 0) ? 3 : cb - 1;
        rb = (qxA + 1 < W1 - 1) ? cb + 2 : (W1 + 1 - qx0);
        ru = (qy == 0) ? 3 : ty + 1;
        rd = (qy < H1 - 1) ? ty + 3 : ty + 2;
    }
    const int rc = ty + 2;

    float FheA[3], FhoA[3], FheB[3], FhoB[3];
    float DheA[3], DhoA[3], DheB[3], DhoB[3];
    int rows[3] = {ru, rc, rd};
#pragma unroll
    for (int i = 0; i < 3; i++) {
        int r = rows[i];
        {
            float2 v01 = *(const float2*)&sF1[r][cb];
            float vl = sF1[r][la], vr = sF1[r][rb];
            FheA[i] = 0.125f * (vl + v01.y) + 0.75f * v01.x;
            FhoA[i] = 0.5f * (v01.x + v01.y);
            FheB[i] = 0.125f * (v01.x + vr) + 0.75f * v01.y;
            FhoB[i] = 0.5f * (v01.y + vr);
        }
        {
            float2 v01 = *(const float2*)&sD1[r][cb];
            float vl = sD1[r][la], vr = sD1[r][rb];
            DheA[i] = 0.125f * (vl + v01.y) + 0.75f * v01.x;
            DhoA[i] = 0.5f * (v01.x + v01.y);
            DheB[i] = 0.125f * (v01.x + vr) + 0.75f * v01.y;
            DhoB[i] = 0.5f * (v01.y + vr);
        }
    }

    const int x0 = 2 * qxA;
    const int y0 = 2 * qy;
    const size_t obase = (size_t)p * (H0 * W0);
    const float* rv = rowv + RO0 + x1_0 + x0;
    float rw0 = rv[0], rw1 = rv[1], rw2 = rv[2], rw3 = rv[3];
    float cw0 = colv[CO0 + y0 + y1_0], cw1 = colv[CO0 + y0 + 1 + y1_0];

    {
        float uF0 = 0.125f * (FheA[0] + FheA[2]) + 0.75f * FheA[1];
        float uF1 = 0.125f * (FhoA[0] + FhoA[2]) + 0.75f * FhoA[1];
        float uF2 = 0.125f * (FheB[0] + FheB[2]) + 0.75f * FheB[1];
        float uF3 = 0.125f * (FhoB[0] + FhoB[2]) + 0.75f * FhoB[1];
        float uD0 = 0.125f * (DheA[0] + DheA[2]) + 0.75f * DheA[1];
        float uD1 = 0.125f * (DhoA[0] + DhoA[2]) + 0.75f * DhoA[1];
        float uD2 = 0.125f * (DheB[0] + DheB[2]) + 0.75f * DheB[1];
        float uD3 = 0.125f * (DhoB[0] + DhoB[2]) + 0.75f * DhoB[1];
        const float4 dc = *(const float4*)(images + obase + (size_t)y0 * W0 + x0);
        float4 o;
        o.x = uF0 + (dc.x - uD0) * (cw0 * rw0);
        o.y = uF1 + (dc.y - uD1) * (cw0 * rw1);
        o.z = uF2 + (dc.z - uD2) * (cw0 * rw2);
        o.w = uF3 + (dc.w - uD3) * (cw0 * rw3);
        *(float4*)(out + obase + (size_t)y0 * W0 + x0) = o;
    }
    {
        float uF0 = 0.5f * (FheA[1] + FheA[2]);
        float uF1 = 0.5f * (FhoA[1] + FhoA[2]);
        float uF2 = 0.5f * (FheB[1] + FheB[2]);
        float uF3 = 0.5f * (FhoB[1] + FhoB[2]);
        float uD0 = 0.5f * (DheA[1] + DheA[2]);
        float uD1 = 0.5f * (DhoA[1] + DhoA[2]);
        float uD2 = 0.5f * (DheB[1] + DheB[2]);
        float uD3 = 0.5f * (DhoB[1] + DhoB[2]);
        const float4 dc = *(const float4*)(images + obase + (size_t)(y0 + 1) * W0 + x0);
        float4 o;
        o.x = uF0 + (dc.x - uD0) * (cw1 * rw0);
        o.y = uF1 + (dc.y - uD1) * (cw1 * rw1);
        o.z = uF2 + (dc.z - uD2) * (cw1 * rw2);
        o.w = uF3 + (dc.w - uD3) * (cw1 * rw3);
        *(float4*)(out + obase + (size_t)(y0 + 1) * W0 + x0) = o;
    }
}

// ---------------------------------------------------------------------------

static inline int idiv(int a, int b) { return (a + b - 1) / b; }

extern "C" void kernel_launch(void* const* d_in, const int* in_sizes, int n_in,
                              void* d_out, int out_size) {
    (void)in_sizes; (void)n_in; (void)out_size;
    const float* images = (const float*)d_in[0];
    const float* fix    = (const float*)d_in[1];
    float* out = (float*)d_out;

    float *rowv, *colv, *dn1, *dn2, *F2;
    cudaGetSymbolAddress((void**)&rowv, g_rowv);
    cudaGetSymbolAddress((void**)&colv, g_colv);
    cudaGetSymbolAddress((void**)&dn1, g_dn1);
    cudaGetSymbolAddress((void**)&dn2, g_dn2);
    cudaGetSymbolAddress((void**)&F2, g_F2);

    cudaFuncSetAttribute(fused_mid_kernel,
                         cudaFuncAttributeMaxDynamicSharedMemorySize,
                         SM_TOT * (int)sizeof(float));

    gen_filters_kernel<<<1, 1024>>>(rowv, colv);

    {
        dim3 blk(16, 16);
        dim3 g1(idiv(W1, PTX), idiv(H1, PTY), NPL);
        pyrdown_st<<<g1, blk>>>(images, dn1, H0, W0, H1, W1);
        dim3 g2(idiv(W2, PTX), idiv(H2, PTY), NPL);
        pyrdown_st<<<g2, blk>>>(dn1, dn2, H1, W1, H2, W2);
    }

    fused_mid_kernel<<<NPL, FNT, SM_TOT * (int)sizeof(float)>>>(
        dn2, colv, rowv, fix, F2);

    {
        dim3 blk(16, 16);
        dim3 g0((W0 / 2) / RQX, idiv(H0 / 2, RQY), NPL);
        recon01<<<g0, blk>>>(F2, dn2, dn1, images, colv, rowv, fix, out);
    }
}

// round 15
// speedup vs baseline: 1.0110x; 1.0110x over previous
#include <cuda_runtime.h>

// ---------------------------------------------------------------------------
// TorchFovea R14: R12 pyrdown (2-wide hpass) + R13 fused_mid vectorization
// + R13 recon01 float2 epilogue. 5 launches.
// ---------------------------------------------------------------------------

#define NPL 96

#define H0 360
#define W0 640
#define H1 180
#define W1 320
#define H2 90
#define W2 160
#define H3 45
#define W3 80
#define H4 23
#define W4 40
#define H5 12
#define W5 20

#define ROWV_TOT (1279 + 640 + 320 + 160 + 80)
#define COLV_TOT (719 + 360 + 180 + 90 + 45)
#define RO0 0
#define RO1 1279
#define RO2 1919
#define RO3 2239
#define RO4 2399
#define CO0 0
#define CO1 719
#define CO2 1079
#define CO3 1259
#define CO4 1349

__device__ float g_rowv[ROWV_TOT];
__device__ float g_colv[COLV_TOT];
__device__ float g_dn1[NPL * H1 * W1];
__device__ float g_dn2[NPL * H2 * W2];
__device__ float g_F2[NPL * H2 * W2];

__device__ __forceinline__ int refl(int i, int n) {
    i = (i < 0) ? -i : i;
    return (i >= n) ? (2 * n - 2 - i) : i;
}

// ---------------------------------------------------------------------------
__device__ __forceinline__ float pd1_at(const float* __restrict__ v, int N, int o) {
    int x = 2 * o;
    return 0.375f * v[x]
         + 0.25f  * (v[refl(x - 1, N)] + v[refl(x + 1, N)])
         + 0.0625f * (v[refl(x - 2, N)] + v[refl(x + 2, N)]);
}

__global__ void gen_filters_kernel(float* __restrict__ rowv, float* __restrict__ colv) {
    const int t = threadIdx.x;
    const int NT = blockDim.x;
    for (int i = t; i < 1279; i += NT) {
        float d = (float)(i - 640);
        rowv[RO0 + i] = expf(-d * d / 10082.0f);
    }
    for (int j = t; j < 719; j += NT) {
        float d = (float)(j - 360);
        colv[CO0 + j] = expf(-d * d / 10082.0f);
    }
    __syncthreads();
    const int rN[5] = {1279, 640, 320, 160, 80};
    const int rO[5] = {RO0, RO1, RO2, RO3, RO4};
    const int cN[5] = {719, 360, 180, 90, 45};
    const int cO[5] = {CO0, CO1, CO2, CO3, CO4};
#pragma unroll
    for (int k = 1; k < 5; k++) {
        const float* ri = rowv + rO[k - 1];
        float* ro = rowv + rO[k];
        for (int o = t; o < rN[k]; o += NT) ro[o] = pd1_at(ri, rN[k - 1], o);
        const float* ci = colv + cO[k - 1];
        float* co = colv + cO[k];
        for (int o = t; o < cN[k]; o += NT) co[o] = pd1_at(ci, cN[k - 1], o);
        __syncthreads();
    }
}

// ---------------------------------------------------------------------------
// pyrDown: block (16,16) -> 32x16 output tile, 2-wide hpass (R12 version).
// ---------------------------------------------------------------------------
#define PTX 32
#define PTY 16
#define PIW (2 * PTX + 4)   // 68
#define PIH (2 * PTY + 4)   // 36

__global__ void __launch_bounds__(256) pyrdown_st(
        const float* __restrict__ src, float* __restrict__ dst,
        int H, int W, int oH, int oW) {
    int c = blockIdx.z;
    const float* s = src + (size_t)c * H * W;
    float* d = dst + (size_t)c * oH * oW;
    int ox0 = blockIdx.x * PTX;
    int oy0 = blockIdx.y * PTY;

    __shared__ float in[PIH][PIW];
    __shared__ float hb[PIH][PTX];

    int tid = threadIdx.y * 16 + threadIdx.x;

    bool interior = (ox0 >= 1) && (2 * ox0 + 65 <= W - 1)
                 && (oy0 >= 1) && (2 * oy0 + 33 <= H - 1);

    if (interior) {
        const float2* s2 = (const float2*)(s + (size_t)(2 * oy0 - 2) * W + (2 * ox0 - 2));
        const int stride2 = W >> 1;
        for (int idx = tid; idx < PIH * (PIW / 2); idx += 256) {
            int r = idx / (PIW / 2);
            int j = idx - r * (PIW / 2);
            *(float2*)&in[r][2 * j] = s2[r * stride2 + j];
        }
    } else {
        for (int idx = tid; idx < PIH * PIW; idx += 256) {
            int r = idx / PIW;
            int col = idx - r * PIW;
            int gy = refl(2 * oy0 - 2 + r, H);
            int gx = refl(2 * ox0 - 2 + col, W);
            in[r][col] = s[(size_t)gy * W + gx];
        }
    }
    __syncthreads();

    const float k0 = 0.0625f, k1 = 0.25f, k2 = 0.375f;
    // horizontal pass: 2 outputs per iteration
    for (int idx = tid; idx < PIH * (PTX / 2); idx += 256) {
        int r = idx >> 4;
        int jj = idx & 15;
        const float* row = in[r] + 4 * jj;
        float2 a  = *(const float2*)(row);
        float2 bb = *(const float2*)(row + 2);
        float2 cc = *(const float2*)(row + 4);
        float  dd = row[6];
        float2 h;
        h.x = k0 * (a.x + cc.x) + k1 * (a.y + bb.y) + k2 * bb.x;
        h.y = k0 * (bb.x + dd) + k1 * (bb.y + cc.y) + k2 * cc.x;
        *(float2*)&hb[r][2 * jj] = h;
    }
    __syncthreads();

    int oy = oy0 + threadIdx.y;
    int ox = ox0 + 2 * threadIdx.x;
    if (oy < oH && ox < oW) {
        int r = 2 * threadIdx.y;
        int j = 2 * threadIdx.x;
        float2 h0 = *(const float2*)&hb[r][j];
        float2 h1 = *(const float2*)&hb[r + 1][j];
        float2 h2 = *(const float2*)&hb[r + 2][j];
        float2 h3 = *(const float2*)&hb[r + 3][j];
        float2 h4 = *(const float2*)&hb[r + 4][j];
        float2 o;
        o.x = k0 * (h0.x + h4.x) + k1 * (h1.x + h3.x) + k2 * h2.x;
        o.y = k0 * (h0.y + h4.y) + k1 * (h1.y + h3.y) + k2 * h2.y;
        *(float2*)(d + (size_t)oy * oW + ox) = o;
    }
}

// ---------------------------------------------------------------------------
__device__ __forceinline__ float pd2_at(const float* __restrict__ s, int H, int W,
                                        int y, int x) {
    int ry[5], rx[5];
#pragma unroll
    for (int i = 0; i < 5; i++) {
        ry[i] = refl(2 * y - 2 + i, H);
        rx[i] = refl(2 * x - 2 + i, W);
    }
    const float k0 = 0.0625f, k1 = 0.25f, k2 = 0.375f;
    float acc = 0.0f;
#pragma unroll
    for (int i = 0; i < 5; i++) {
        const float* row = s + ry[i] * W;
        float r = k2 * row[rx[2]]
                + k1 * (row[rx[1]] + row[rx[3]])
                + k0 * (row[rx[0]] + row[rx[4]]);
        float kw = (i == 2) ? k2 : ((i == 1 || i == 3) ? k1 : k0);
        acc += kw * r;
    }
    return acc;
}

__device__ __forceinline__ void pyrup_quad(const float* __restrict__ s, int H, int W,
                                           int qy, int qx,
                                           float& ee, float& eo, float& oe, float& oo) {
    int xl = (qx == 0) ? 1 : qx - 1;
    int xr = (qx < W - 1) ? qx + 1 : W - 1;
    int yu = (qy == 0) ? 1 : qy - 1;
    int yd = (qy < H - 1) ? qy + 1 : H - 1;
    const float* r0 = s + yu * W;
    const float* r1 = s + qy * W;
    const float* r2 = s + yd * W;
    float a00 = r0[xl], a01 = r0[qx], a02 = r0[xr];
    float a10 = r1[xl], a11 = r1[qx], a12 = r1[xr];
    float a20 = r2[xl], a21 = r2[qx], a22 = r2[xr];
    float he0 = 0.125f * (a00 + a02) + 0.75f * a01;
    float he1 = 0.125f * (a10 + a12) + 0.75f * a11;
    float he2 = 0.125f * (a20 + a22) + 0.75f * a21;
    float ho0 = 0.5f * (a01 + a02);
    float ho1 = 0.5f * (a11 + a12);
    float ho2 = 0.5f * (a21 + a22);
    ee = 0.125f * (he0 + he2) + 0.75f * he1;
    eo = 0.125f * (ho0 + ho2) + 0.75f * ho1;
    oe = 0.5f * (he1 + he2);
    oo = 0.5f * (ho1 + ho2);
}

// ---------------------------------------------------------------------------
// Fused mid levels: vectorized hb3 (3 loads) and paired-column dn3 (R13).
// ---------------------------------------------------------------------------
#define FNT 1024
#define SM_DN2 0
#define SM_HB3 14400
#define SM_DN3 21600
#define SM_DN4 25200
#define SM_DN5 26120
#define SM_F4  26360
#define SM_TOT 27280

__global__ void __launch_bounds__(FNT) fused_mid_kernel(
        const float* __restrict__ dn2,
        const float* __restrict__ colv, const float* __restrict__ rowv,
        const float* __restrict__ fixations,
        float* __restrict__ F2g) {
    extern __shared__ float sm[];
    float* s_dn2 = sm + SM_DN2;
    float* s_hb3 = sm + SM_HB3;
    float* s_F3  = sm + SM_HB3;
    float* s_dn3 = sm + SM_DN3;
    float* s_dn4 = sm + SM_DN4;
    float* s_dn5 = sm + SM_DN5;
    float* s_F4  = sm + SM_F4;

    const int p = blockIdx.x;
    const int b = p / 3;
    const int t = threadIdx.x;
    const float k0 = 0.0625f, k1 = 0.25f, k2 = 0.375f;

    const float4* src4 = (const float4*)(dn2 + (size_t)p * (H2 * W2));
    for (int i = t; i < (H2 * W2) / 4; i += FNT) ((float4*)s_dn2)[i] = src4[i];
    __syncthreads();

    // hb3 (90 x 80)
    for (int idx = t; idx < H2 * W3; idx += FNT) {
        int y = idx / W3;
        int ox = idx - y * W3;
        const float* row = s_dn2 + y * W2;
        int xc = 2 * ox;
        float v;
        if (ox >= 1 && ox <= W3 - 2) {
            float2 m = *(const float2*)(row + xc - 2);
            float2 n = *(const float2*)(row + xc);
            v = k0 * (m.x + row[xc + 2]) + k1 * (m.y + n.y) + k2 * n.x;
        } else {
            v = k2 * row[xc]
              + k1 * (row[refl(xc - 1, W2)] + row[refl(xc + 1, W2)])
              + k0 * (row[refl(xc - 2, W2)] + row[refl(xc + 2, W2)]);
        }
        s_hb3[idx] = v;
    }
    __syncthreads();

    // dn3 (45 x 80): paired columns, float2 loads/stores
    for (int idx = t; idx < H3 * (W3 / 2); idx += FNT) {
        int oy = idx / (W3 / 2);
        int oxp = idx - oy * (W3 / 2);
        int yc = 2 * oy;
        int r0, r1, r3, r4;
        if (oy >= 1 && oy <= H3 - 2) {
            r0 = yc - 2; r1 = yc - 1; r3 = yc + 1; r4 = yc + 2;
        } else {
            r0 = refl(yc - 2, H2); r1 = refl(yc - 1, H2);
            r3 = refl(yc + 1, H2); r4 = refl(yc + 2, H2);
        }
        int col = 2 * oxp;
        float2 h0 = *(const float2*)&s_hb3[r0 * W3 + col];
        float2 h1 = *(const float2*)&s_hb3[r1 * W3 + col];
        float2 h2 = *(const float2*)&s_hb3[yc * W3 + col];
        float2 h3 = *(const float2*)&s_hb3[r3 * W3 + col];
        float2 h4 = *(const float2*)&s_hb3[r4 * W3 + col];
        float2 v;
        v.x = k0 * (h0.x + h4.x) + k1 * (h1.x + h3.x) + k2 * h2.x;
        v.y = k0 * (h0.y + h4.y) + k1 * (h1.y + h3.y) + k2 * h2.y;
        *(float2*)&s_dn3[oy * W3 + col] = v;
    }
    __syncthreads();

    for (int idx = t; idx < H4 * W4; idx += FNT)
        s_dn4[idx] = pd2_at(s_dn3, H3, W3, idx / W4, idx % W4);
    __syncthreads();
    for (int idx = t; idx < H5 * W5; idx += FNT)
        s_dn5[idx] = pd2_at(s_dn4, H4, W4, idx / W5, idx % W5);
    __syncthreads();

    const float fxx = fixations[2 * b];
    const float fyy = fixations[2 * b + 1];

    {   // level 4
        int x1 = min(max((int)(40.0f - fxx * 0.0625f), 0), W3 - W4);
        int y1 = min(max((int)(22.5f - fyy * 0.0625f), 0), H3 - H4);
        const float* cv = colv + CO4 + y1;
        const float* rv = rowv + RO4 + x1;
        const int qH = (H4 + 1) / 2, qW = W4 / 2;
        for (int idx = t; idx < qH * qW; idx += FNT) {
            int qy = idx / qW;
            int qx = idx - qy * qW;
            float ee, eo, oe, oo;
            pyrup_quad(s_dn5, H5, W5, qy, qx, ee, eo, oe, oo);
            int y0 = 2 * qy, x0 = 2 * qx;
            float rw0 = rv[x0], rw1 = rv[x0 + 1];
            float cw0 = cv[y0];
            s_F4[y0 * W4 + x0]     = ee + (s_dn4[y0 * W4 + x0]     - ee) * (cw0 * rw0);
            s_F4[y0 * W4 + x0 + 1] = eo + (s_dn4[y0 * W4 + x0 + 1] - eo) * (cw0 * rw1);
            if (y0 + 1 < H4) {
                float cw1 = cv[y0 + 1];
                s_F4[(y0 + 1) * W4 + x0]     = oe + (s_dn4[(y0 + 1) * W4 + x0]     - oe) * (cw1 * rw0);
                s_F4[(y0 + 1) * W4 + x0 + 1] = oo + (s_dn4[(y0 + 1) * W4 + x0 + 1] - oo) * (cw1 * rw1);
            }
        }
    }
    __syncthreads();

    {   // level 3
        int x1 = min(max((int)(80.0f - fxx * 0.125f), 0), W2 - W3);
        int y1 = min(max((int)(45.0f - fyy * 0.125f), 0), H2 - H3);
        const float* cv = colv + CO3 + y1;
        const float* rv = rowv + RO3 + x1;
        const int qH = (H3 + 1) / 2, qW = W3 / 2;
        for (int idx = t; idx < qH * qW; idx += FNT) {
            int qy = idx / qW;
            int qx = idx - qy * qW;
            float Fee, Feo, Foe, Foo, Dee, Deo, Doe, Doo;
            pyrup_quad(s_F4, H4, W4, qy, qx, Fee, Feo, Foe, Foo);
            pyrup_quad(s_dn4, H4, W4, qy, qx, Dee, Deo, Doe, Doo);
            int y0 = 2 * qy, x0 = 2 * qx;
            float rw0 = rv[x0], rw1 = rv[x0 + 1];
            float cw0 = cv[y0];
            s_F3[y0 * W3 + x0]     = Fee + (s_dn3[y0 * W3 + x0]     - Dee) * (cw0 * rw0);
            s_F3[y0 * W3 + x0 + 1] = Feo + (s_dn3[y0 * W3 + x0 + 1] - Deo) * (cw0 * rw1);
            if (y0 + 1 < H3) {
                float cw1 = cv[y0 + 1];
                s_F3[(y0 + 1) * W3 + x0]     = Foe + (s_dn3[(y0 + 1) * W3 + x0]     - Doe) * (cw1 * rw0);
                s_F3[(y0 + 1) * W3 + x0 + 1] = Foo + (s_dn3[(y0 + 1) * W3 + x0 + 1] - Doo) * (cw1 * rw1);
            }
        }
    }
    __syncthreads();

    {   // level 2 -> global F2
        int x1 = min(max((int)(160.0f - fxx * 0.25f), 0), W1 - W2);
        int y1 = min(max((int)(90.0f - fyy * 0.25f), 0), H1 - H2);
        const float* cv = colv + CO2 + y1;
        const float* rv = rowv + RO2 + x1;
        float* g = F2g + (size_t)p * (H2 * W2);
        const int qH = H2 / 2, qW = W2 / 2;
        for (int idx = t; idx < qH * qW; idx += FNT) {
            int qy = idx / qW;
            int qx = idx - qy * qW;
            float Fee, Feo, Foe, Foo, Dee, Deo, Doe, Doo;
            pyrup_quad(s_F3, H3, W3, qy, qx, Fee, Feo, Foe, Foo);
            pyrup_quad(s_dn3, H3, W3, qy, qx, Dee, Deo, Doe, Doo);
            int y0 = 2 * qy, x0 = 2 * qx;
            float rw0 = rv[x0], rw1 = rv[x0 + 1];
            float cw0 = cv[y0], cw1 = cv[y0 + 1];
            float2 o0, o1;
            o0.x = Fee + (s_dn2[y0 * W2 + x0]     - Dee) * (cw0 * rw0);
            o0.y = Feo + (s_dn2[y0 * W2 + x0 + 1] - Deo) * (cw0 * rw1);
            o1.x = Foe + (s_dn2[(y0 + 1) * W2 + x0]     - Doe) * (cw1 * rw0);
            o1.y = Foo + (s_dn2[(y0 + 1) * W2 + x0 + 1] - Doo) * (cw1 * rw1);
            *(float2*)(g + y0 * W2 + x0) = o0;
            *(float2*)(g + (y0 + 1) * W2 + x0) = o1;
        }
    }
}

// ---------------------------------------------------------------------------
// recon01 with interior fast path; epilogue uses float2 center loads.
// Block (16,16) -> 64x32 output pixels.
// ---------------------------------------------------------------------------
#define RQX 32
#define RQY 16

__global__ void __launch_bounds__(256) recon01(
        const float* __restrict__ F2,
        const float* __restrict__ dn2,
        const float* __restrict__ dn1,
        const float* __restrict__ images,
        const float* __restrict__ colv,
        const float* __restrict__ rowv,
        const float* __restrict__ fixations,
        float* __restrict__ out) {
    __shared__ float sD1[20][36];
    __shared__ float sF1[20][36];
    __shared__ float sF2[12][20];
    __shared__ float sD2[12][20];

    const int p = blockIdx.z;
    const int b = p / 3;
    const int qx0 = blockIdx.x * RQX;
    const int qy0 = blockIdx.y * RQY;
    const int tid = threadIdx.y * 16 + threadIdx.x;

    const float fxx = fixations[2 * b];
    const float fyy = fixations[2 * b + 1];
    const int x1_0 = min(max((int)(639.5f - fxx), 0), 1279 - W0);
    const int y1_0 = min(max((int)(359.5f - fyy), 0), 719 - H0);
    const int x1_1 = min(max((int)(320.0f - fxx * 0.5f), 0), W0 - W1);
    const int y1_1 = min(max((int)(180.0f - fyy * 0.5f), 0), H0 - H1);

    const int base1y = qy0 - 2, base1x = qx0 - 2;
    const int base2y = (qy0 >> 1) - 2, base2x = (qx0 >> 1) - 2;

    const bool interior = (qx0 >= 2) && (qx0 + 34 <= W1) && (qx0 / 2 + 18 <= W2)
                       && (qy0 >= 2) && (qy0 + 18 <= H1) && (qy0 / 2 + 10 <= H2);

    // ---- stage ---------------------------------------------------------------
    if (interior) {
        const float2* p1 = (const float2*)(dn1 + (size_t)p * (H1 * W1)
                                           + (size_t)base1y * W1 + base1x);
        const int st1 = W1 >> 1;
        for (int i = tid; i < 20 * 18; i += 256) {
            int r = i / 18;
            int j = i - r * 18;
            *(float2*)&sD1[r][2 * j] = p1[r * st1 + j];
        }
        const size_t off2 = (size_t)p * (H2 * W2) + (size_t)base2y * W2 + base2x;
        const float2* pf = (const float2*)(F2 + off2);
        const float2* pd = (const float2*)(dn2 + off2);
        const int st2 = W2 >> 1;
        for (int i = tid; i < 12 * 10; i += 256) {
            int r = i / 10;
            int j = i - r * 10;
            *(float2*)&sF2[r][2 * j] = pf[r * st2 + j];
            *(float2*)&sD2[r][2 * j] = pd[r * st2 + j];
        }
    } else {
        const float* s1 = dn1 + (size_t)p * (H1 * W1);
        for (int i = tid; i < 20 * 36; i += 256) {
            int r = i / 36;
            int c = i - r * 36;
            int gr = min(max(base1y + r, 0), H1 - 1);
            int gc = min(max(base1x + c, 0), W1 - 1);
            sD1[r][c] = s1[(size_t)gr * W1 + gc];
        }
        const float* sf = F2 + (size_t)p * (H2 * W2);
        const float* sd = dn2 + (size_t)p * (H2 * W2);
        for (int i = tid; i < 12 * 20; i += 256) {
            int r = i / 20;
            int c = i - r * 20;
            int gr = min(max(base2y + r, 0), H2 - 1);
            int gc = min(max(base2x + c, 0), W2 - 1);
            size_t off = (size_t)gr * W2 + gc;
            sF2[r][c] = sf[off];
            sD2[r][c] = sd[off];
        }
    }
    __syncthreads();

    // ---- F1 tile: 10x18 quads ------------------------------------------------
    {
        const float* cv1 = colv + CO1 + y1_1;
        const float* rv1 = rowv + RO1 + x1_1;
        const int Qy0 = (qy0 >> 1) - 1;
        const int Qx0 = (qx0 >> 1) - 1;
        if (interior) {
            for (int i = tid; i < 10 * 18; i += 256) {
                int qr = i / 18;
                int qc = i - qr * 18;
                float Fee, Feo, Foe, Foo, Dee, Deo, Doe, Doo;
                {
                    float a00 = sF2[qr][qc],     a01 = sF2[qr][qc + 1],     a02 = sF2[qr][qc + 2];
                    float a10 = sF2[qr + 1][qc], a11 = sF2[qr + 1][qc + 1], a12 = sF2[qr + 1][qc + 2];
                    float a20 = sF2[qr + 2][qc], a21 = sF2[qr + 2][qc + 1], a22 = sF2[qr + 2][qc + 2];
                    float he0 = 0.125f * (a00 + a02) + 0.75f * a01;
                    float he1 = 0.125f * (a10 + a12) + 0.75f * a11;
                    float he2 = 0.125f * (a20 + a22) + 0.75f * a21;
                    float ho0 = 0.5f * (a01 + a02);
                    float ho1 = 0.5f * (a11 + a12);
                    float ho2 = 0.5f * (a21 + a22);
                    Fee = 0.125f * (he0 + he2) + 0.75f * he1;
                    Feo = 0.125f * (ho0 + ho2) + 0.75f * ho1;
                    Foe = 0.5f * (he1 + he2);
                    Foo = 0.5f * (ho1 + ho2);
                }
                {
                    float a00 = sD2[qr][qc],     a01 = sD2[qr][qc + 1],     a02 = sD2[qr][qc + 2];
                    float a10 = sD2[qr + 1][qc], a11 = sD2[qr + 1][qc + 1], a12 = sD2[qr + 1][qc + 2];
                    float a20 = sD2[qr + 2][qc], a21 = sD2[qr + 2][qc + 1], a22 = sD2[qr + 2][qc + 2];
                    float he0 = 0.125f * (a00 + a02) + 0.75f * a01;
                    float he1 = 0.125f * (a10 + a12) + 0.75f * a11;
                    float he2 = 0.125f * (a20 + a22) + 0.75f * a21;
                    float ho0 = 0.5f * (a01 + a02);
                    float ho1 = 0.5f * (a11 + a12);
                    float ho2 = 0.5f * (a21 + a22);
                    Dee = 0.125f * (he0 + he2) + 0.75f * he1;
                    Deo = 0.125f * (ho0 + ho2) + 0.75f * ho1;
                    Doe = 0.5f * (he1 + he2);
                    Doo = 0.5f * (ho1 + ho2);
                }
                int gy = 2 * (Qy0 + qr), gx = 2 * (Qx0 + qc);
                int r0 = 2 * qr;
                int c0 = 2 * qc;
                float cw0 = cv1[gy], cw1 = cv1[gy + 1];
                float rw0 = rv1[gx], rw1 = rv1[gx + 1];
                float2 d0 = *(const float2*)&sD1[r0][c0];
                float2 d1 = *(const float2*)&sD1[r0 + 1][c0];
                float2 f0, f1;
                f0.x = Fee + (d0.x - Dee) * (cw0 * rw0);
                f0.y = Feo + (d0.y - Deo) * (cw0 * rw1);
                f1.x = Foe + (d1.x - Doe) * (cw1 * rw0);
                f1.y = Foo + (d1.y - Doo) * (cw1 * rw1);
                *(float2*)&sF1[r0][c0]     = f0;
                *(float2*)&sF1[r0 + 1][c0] = f1;
            }
        } else {
            for (int i = tid; i < 10 * 18; i += 256) {
                int qr = i / 18;
                int qc = i - qr * 18;
                int Qy = Qy0 + qr;
                int Qx = Qx0 + qc;
                if (Qy < 0 || Qy >= H2 || Qx < 0 || Qx >= W2) continue;

                int yu = ((Qy == 0) ? 1 : Qy - 1) - base2y;
                int yc = Qy - base2y;
                int yd = ((Qy < H2 - 1) ? Qy + 1 : H2 - 1) - base2y;
                int xl = ((Qx == 0) ? 1 : Qx - 1) - base2x;
                int xc = Qx - base2x;
                int xr = ((Qx < W2 - 1) ? Qx + 1 : W2 - 1) - base2x;

                float Fee, Feo, Foe, Foo, Dee, Deo, Doe, Doo;
                {
                    float a00 = sF2[yu][xl], a01 = sF2[yu][xc], a02 = sF2[yu][xr];
                    float a10 = sF2[yc][xl], a11 = sF2[yc][xc], a12 = sF2[yc][xr];
                    float a20 = sF2[yd][xl], a21 = sF2[yd][xc], a22 = sF2[yd][xr];
                    float he0 = 0.125f * (a00 + a02) + 0.75f * a01;
                    float he1 = 0.125f * (a10 + a12) + 0.75f * a11;
                    float he2 = 0.125f * (a20 + a22) + 0.75f * a21;
                    float ho0 = 0.5f * (a01 + a02);
                    float ho1 = 0.5f * (a11 + a12);
                    float ho2 = 0.5f * (a21 + a22);
                    Fee = 0.125f * (he0 + he2) + 0.75f * he1;
                    Feo = 0.125f * (ho0 + ho2) + 0.75f * ho1;
                    Foe = 0.5f * (he1 + he2);
                    Foo = 0.5f * (ho1 + ho2);
                }
                {
                    float a00 = sD2[yu][xl], a01 = sD2[yu][xc], a02 = sD2[yu][xr];
                    float a10 = sD2[yc][xl], a11 = sD2[yc][xc], a12 = sD2[yc][xr];
                    float a20 = sD2[yd][xl], a21 = sD2[yd][xc], a22 = sD2[yd][xr];
                    float he0 = 0.125f * (a00 + a02) + 0.75f * a01;
                    float he1 = 0.125f * (a10 + a12) + 0.75f * a11;
                    float he2 = 0.125f * (a20 + a22) + 0.75f * a21;
                    float ho0 = 0.5f * (a01 + a02);
                    float ho1 = 0.5f * (a11 + a12);
                    float ho2 = 0.5f * (a21 + a22);
                    Dee = 0.125f * (he0 + he2) + 0.75f * he1;
                    Deo = 0.125f * (ho0 + ho2) + 0.75f * ho1;
                    Doe = 0.5f * (he1 + he2);
                    Doo = 0.5f * (ho1 + ho2);
                }

                int gy = 2 * Qy, gx = 2 * Qx;
                int r0 = gy - base1y;
                int c0 = gx - base1x;
                float cw0 = cv1[gy], cw1 = cv1[gy + 1];
                float rw0 = rv1[gx], rw1 = rv1[gx + 1];
                sF1[r0][c0]         = Fee + (sD1[r0][c0]         - Dee) * (cw0 * rw0);
                sF1[r0][c0 + 1]     = Feo + (sD1[r0][c0 + 1]     - Deo) * (cw0 * rw1);
                sF1[r0 + 1][c0]     = Foe + (sD1[r0 + 1][c0]     - Doe) * (cw1 * rw0);
                sF1[r0 + 1][c0 + 1] = Foo + (sD1[r0 + 1][c0 + 1] - Doo) * (cw1 * rw1);
            }
        }
    }
    __syncthreads();

    // ---- level-0 recon: two quads per thread, float4 rows -------------------
    const int ty = threadIdx.y;
    const int qy = qy0 + ty;
    if (qy >= H1) return;
    const int qxA = qx0 + 2 * threadIdx.x;

    const int cb = 2 * threadIdx.x + 2;
    int la, rb, ru, rd;
    if (interior) {
        la = cb - 1;
        rb = cb + 2;
        ru = ty + 1;
        rd = ty + 3;
    } else {
        la = (qxA == 0) ? 3 : cb - 1;
        rb = (qxA + 1 < W1 - 1) ? cb + 2 : (W1 + 1 - qx0);
        ru = (qy == 0) ? 3 : ty + 1;
        rd = (qy < H1 - 1) ? ty + 3 : ty + 2;
    }
    const int rc = ty + 2;

    float FheA[3], FhoA[3], FheB[3], FhoB[3];
    float DheA[3], DhoA[3], DheB[3], DhoB[3];
    int rows[3] = {ru, rc, rd};
#pragma unroll
    for (int i = 0; i < 3; i++) {
        int r = rows[i];
        {
            float2 v01 = *(const float2*)&sF1[r][cb];
            float vl = sF1[r][la], vr = sF1[r][rb];
            FheA[i] = 0.125f * (vl + v01.y) + 0.75f * v01.x;
            FhoA[i] = 0.5f * (v01.x + v01.y);
            FheB[i] = 0.125f * (v01.x + vr) + 0.75f * v01.y;
            FhoB[i] = 0.5f * (v01.y + vr);
        }
        {
            float2 v01 = *(const float2*)&sD1[r][cb];
            float vl = sD1[r][la], vr = sD1[r][rb];
            DheA[i] = 0.125f * (vl + v01.y) + 0.75f * v01.x;
            DhoA[i] = 0.5f * (v01.x + v01.y);
            DheB[i] = 0.125f * (v01.x + vr) + 0.75f * v01.y;
            DhoB[i] = 0.5f * (v01.y + vr);
        }
    }

    const int x0 = 2 * qxA;
    const int y0 = 2 * qy;
    const size_t obase = (size_t)p * (H0 * W0);
    const float* rv = rowv + RO0 + x1_0 + x0;
    float rw0 = rv[0], rw1 = rv[1], rw2 = rv[2], rw3 = rv[3];
    float cw0 = colv[CO0 + y0 + y1_0], cw1 = colv[CO0 + y0 + 1 + y1_0];

    {
        float uF0 = 0.125f * (FheA[0] + FheA[2]) + 0.75f * FheA[1];
        float uF1 = 0.125f * (FhoA[0] + FhoA[2]) + 0.75f * FhoA[1];
        float uF2 = 0.125f * (FheB[0] + FheB[2]) + 0.75f * FheB[1];
        float uF3 = 0.125f * (FhoB[0] + FhoB[2]) + 0.75f * FhoB[1];
        float uD0 = 0.125f * (DheA[0] + DheA[2]) + 0.75f * DheA[1];
        float uD1 = 0.125f * (DhoA[0] + DhoA[2]) + 0.75f * DhoA[1];
        float uD2 = 0.125f * (DheB[0] + DheB[2]) + 0.75f * DheB[1];
        float uD3 = 0.125f * (DhoB[0] + DhoB[2]) + 0.75f * DhoB[1];
        const float4 dc = *(const float4*)(images + obase + (size_t)y0 * W0 + x0);
        float4 o;
        o.x = uF0 + (dc.x - uD0) * (cw0 * rw0);
        o.y = uF1 + (dc.y - uD1) * (cw0 * rw1);
        o.z = uF2 + (dc.z - uD2) * (cw0 * rw2);
        o.w = uF3 + (dc.w - uD3) * (cw0 * rw3);
        *(float4*)(out + obase + (size_t)y0 * W0 + x0) = o;
    }
    {
        float uF0 = 0.5f * (FheA[1] + FheA[2]);
        float uF1 = 0.5f * (FhoA[1] + FhoA[2]);
        float uF2 = 0.5f * (FheB[1] + FheB[2]);
        float uF3 = 0.5f * (FhoB[1] + FhoB[2]);
        float uD0 = 0.5f * (DheA[1] + DheA[2]);
        float uD1 = 0.5f * (DhoA[1] + DhoA[2]);
        float uD2 = 0.5f * (DheB[1] + DheB[2]);
        float uD3 = 0.5f * (DhoB[1] + DhoB[2]);
        const float4 dc = *(const float4*)(images + obase + (size_t)(y0 + 1) * W0 + x0);
        float4 o;
        o.x = uF0 + (dc.x - uD0) * (cw1 * rw0);
        o.y = uF1 + (dc.y - uD1) * (cw1 * rw1);
        o.z = uF2 + (dc.z - uD2) * (cw1 * rw2);
        o.w = uF3 + (dc.w - uD3) * (cw1 * rw3);
        *(float4*)(out + obase + (size_t)(y0 + 1) * W0 + x0) = o;
    }
}

// ---------------------------------------------------------------------------

static inline int idiv(int a, int b) { return (a + b - 1) / b; }

extern "C" void kernel_launch(void* const* d_in, const int* in_sizes, int n_in,
                              void* d_out, int out_size) {
    (void)in_sizes; (void)n_in; (void)out_size;
    const float* images = (const float*)d_in[0];
    const float* fix    = (const float*)d_in[1];
    float* out = (float*)d_out;

    float *rowv, *colv, *dn1, *dn2, *F2;
    cudaGetSymbolAddress((void**)&rowv, g_rowv);
    cudaGetSymbolAddress((void**)&colv, g_colv);
    cudaGetSymbolAddress((void**)&dn1, g_dn1);
    cudaGetSymbolAddress((void**)&dn2, g_dn2);
    cudaGetSymbolAddress((void**)&F2, g_F2);

    cudaFuncSetAttribute(fused_mid_kernel,
                         cudaFuncAttributeMaxDynamicSharedMemorySize,
                         SM_TOT * (int)sizeof(float));

    gen_filters_kernel<<<1, 1024>>>(rowv, colv);

    {
        dim3 blk(16, 16);
        dim3 g1(idiv(W1, PTX), idiv(H1, PTY), NPL);
        pyrdown_st<<<g1, blk>>>(images, dn1, H0, W0, H1, W1);
        dim3 g2(idiv(W2, PTX), idiv(H2, PTY), NPL);
        pyrdown_st<<<g2, blk>>>(dn1, dn2, H1, W1, H2, W2);
    }

    fused_mid_kernel<<<NPL, FNT, SM_TOT * (int)sizeof(float)>>>(
        dn2, colv, rowv, fix, F2);

    {
        dim3 blk(16, 16);
        dim3 g0((W0 / 2) / RQX, idiv(H0 / 2, RQY), NPL);
        recon01<<<g0, blk>>>(F2, dn2, dn1, images, colv, rowv, fix, out);
    }
}

// round 16
// speedup vs baseline: 1.0534x; 1.0419x over previous
#include <cuda_runtime.h>

// ---------------------------------------------------------------------------
// TorchFovea R15: R12 base + R13 fused_mid vectorization + filter generation
// folded into the pyrdown1 launch (extra grid.z slice). 4 launches.
// ---------------------------------------------------------------------------

#define NPL 96

#define H0 360
#define W0 640
#define H1 180
#define W1 320
#define H2 90
#define W2 160
#define H3 45
#define W3 80
#define H4 23
#define W4 40
#define H5 12
#define W5 20

#define ROWV_TOT (1279 + 640 + 320 + 160 + 80)
#define COLV_TOT (719 + 360 + 180 + 90 + 45)
#define RO0 0
#define RO1 1279
#define RO2 1919
#define RO3 2239
#define RO4 2399
#define CO0 0
#define CO1 719
#define CO2 1079
#define CO3 1259
#define CO4 1349

__device__ float g_rowv[ROWV_TOT];
__device__ float g_colv[COLV_TOT];
__device__ float g_dn1[NPL * H1 * W1];
__device__ float g_dn2[NPL * H2 * W2];
__device__ float g_F2[NPL * H2 * W2];

__device__ __forceinline__ int refl(int i, int n) {
    i = (i < 0) ? -i : i;
    return (i >= n) ? (2 * n - 2 - i) : i;
}

// ---------------------------------------------------------------------------
__device__ __forceinline__ float pd1_at(const float* __restrict__ v, int N, int o) {
    int x = 2 * o;
    return 0.375f * v[x]
         + 0.25f  * (v[refl(x - 1, N)] + v[refl(x + 1, N)])
         + 0.0625f * (v[refl(x - 2, N)] + v[refl(x + 2, N)]);
}

// all 1D fovea filters, run by one 256-thread block
__device__ void gen_filters_block(float* __restrict__ rowv, float* __restrict__ colv) {
    const int t = threadIdx.y * 16 + threadIdx.x;
    const int NT = 256;
    for (int i = t; i < 1279; i += NT) {
        float d = (float)(i - 640);
        rowv[RO0 + i] = expf(-d * d / 10082.0f);
    }
    for (int j = t; j < 719; j += NT) {
        float d = (float)(j - 360);
        colv[CO0 + j] = expf(-d * d / 10082.0f);
    }
    __syncthreads();
    const int rN[5] = {1279, 640, 320, 160, 80};
    const int rO[5] = {RO0, RO1, RO2, RO3, RO4};
    const int cN[5] = {719, 360, 180, 90, 45};
    const int cO[5] = {CO0, CO1, CO2, CO3, CO4};
#pragma unroll
    for (int k = 1; k < 5; k++) {
        const float* ri = rowv + rO[k - 1];
        float* ro = rowv + rO[k];
        for (int o = t; o < rN[k]; o += NT) ro[o] = pd1_at(ri, rN[k - 1], o);
        const float* ci = colv + cO[k - 1];
        float* co = colv + cO[k];
        for (int o = t; o < cN[k]; o += NT) co[o] = pd1_at(ci, cN[k - 1], o);
        __syncthreads();
    }
}

// ---------------------------------------------------------------------------
// pyrDown: block (16,16) -> 32x16 output tile, 2-wide hpass (R12 version).
// If do_filt != 0, grid.z has one extra slice: block (0,0,NPL) generates the
// separable fovea filters; other z==NPL blocks exit.
// ---------------------------------------------------------------------------
#define PTX 32
#define PTY 16
#define PIW (2 * PTX + 4)   // 68
#define PIH (2 * PTY + 4)   // 36

__global__ void __launch_bounds__(256) pyrdown_st(
        const float* __restrict__ src, float* __restrict__ dst,
        int H, int W, int oH, int oW,
        float* __restrict__ rowv, float* __restrict__ colv, int nplanes) {
    int c = blockIdx.z;
    if (c >= nplanes) {
        if (blockIdx.x == 0 && blockIdx.y == 0) gen_filters_block(rowv, colv);
        return;
    }
    const float* s = src + (size_t)c * H * W;
    float* d = dst + (size_t)c * oH * oW;
    int ox0 = blockIdx.x * PTX;
    int oy0 = blockIdx.y * PTY;

    __shared__ float in[PIH][PIW];
    __shared__ float hb[PIH][PTX];

    int tid = threadIdx.y * 16 + threadIdx.x;

    bool interior = (ox0 >= 1) && (2 * ox0 + 65 <= W - 1)
                 && (oy0 >= 1) && (2 * oy0 + 33 <= H - 1);

    if (interior) {
        const float2* s2 = (const float2*)(s + (size_t)(2 * oy0 - 2) * W + (2 * ox0 - 2));
        const int stride2 = W >> 1;
        for (int idx = tid; idx < PIH * (PIW / 2); idx += 256) {
            int r = idx / (PIW / 2);
            int j = idx - r * (PIW / 2);
            *(float2*)&in[r][2 * j] = s2[r * stride2 + j];
        }
    } else {
        for (int idx = tid; idx < PIH * PIW; idx += 256) {
            int r = idx / PIW;
            int col = idx - r * PIW;
            int gy = refl(2 * oy0 - 2 + r, H);
            int gx = refl(2 * ox0 - 2 + col, W);
            in[r][col] = s[(size_t)gy * W + gx];
        }
    }
    __syncthreads();

    const float k0 = 0.0625f, k1 = 0.25f, k2 = 0.375f;
    for (int idx = tid; idx < PIH * (PTX / 2); idx += 256) {
        int r = idx >> 4;
        int jj = idx & 15;
        const float* row = in[r] + 4 * jj;
        float2 a  = *(const float2*)(row);
        float2 bb = *(const float2*)(row + 2);
        float2 cc = *(const float2*)(row + 4);
        float  dd = row[6];
        float2 h;
        h.x = k0 * (a.x + cc.x) + k1 * (a.y + bb.y) + k2 * bb.x;
        h.y = k0 * (bb.x + dd) + k1 * (bb.y + cc.y) + k2 * cc.x;
        *(float2*)&hb[r][2 * jj] = h;
    }
    __syncthreads();

    int oy = oy0 + threadIdx.y;
    int ox = ox0 + 2 * threadIdx.x;
    if (oy < oH && ox < oW) {
        int r = 2 * threadIdx.y;
        int j = 2 * threadIdx.x;
        float2 h0 = *(const float2*)&hb[r][j];
        float2 h1 = *(const float2*)&hb[r + 1][j];
        float2 h2 = *(const float2*)&hb[r + 2][j];
        float2 h3 = *(const float2*)&hb[r + 3][j];
        float2 h4 = *(const float2*)&hb[r + 4][j];
        float2 o;
        o.x = k0 * (h0.x + h4.x) + k1 * (h1.x + h3.x) + k2 * h2.x;
        o.y = k0 * (h0.y + h4.y) + k1 * (h1.y + h3.y) + k2 * h2.y;
        *(float2*)(d + (size_t)oy * oW + ox) = o;
    }
}

// ---------------------------------------------------------------------------
__device__ __forceinline__ float pd2_at(const float* __restrict__ s, int H, int W,
                                        int y, int x) {
    int ry[5], rx[5];
#pragma unroll
    for (int i = 0; i < 5; i++) {
        ry[i] = refl(2 * y - 2 + i, H);
        rx[i] = refl(2 * x - 2 + i, W);
    }
    const float k0 = 0.0625f, k1 = 0.25f, k2 = 0.375f;
    float acc = 0.0f;
#pragma unroll
    for (int i = 0; i < 5; i++) {
        const float* row = s + ry[i] * W;
        float r = k2 * row[rx[2]]
                + k1 * (row[rx[1]] + row[rx[3]])
                + k0 * (row[rx[0]] + row[rx[4]]);
        float kw = (i == 2) ? k2 : ((i == 1 || i == 3) ? k1 : k0);
        acc += kw * r;
    }
    return acc;
}

__device__ __forceinline__ void pyrup_quad(const float* __restrict__ s, int H, int W,
                                           int qy, int qx,
                                           float& ee, float& eo, float& oe, float& oo) {
    int xl = (qx == 0) ? 1 : qx - 1;
    int xr = (qx < W - 1) ? qx + 1 : W - 1;
    int yu = (qy == 0) ? 1 : qy - 1;
    int yd = (qy < H - 1) ? qy + 1 : H - 1;
    const float* r0 = s + yu * W;
    const float* r1 = s + qy * W;
    const float* r2 = s + yd * W;
    float a00 = r0[xl], a01 = r0[qx], a02 = r0[xr];
    float a10 = r1[xl], a11 = r1[qx], a12 = r1[xr];
    float a20 = r2[xl], a21 = r2[qx], a22 = r2[xr];
    float he0 = 0.125f * (a00 + a02) + 0.75f * a01;
    float he1 = 0.125f * (a10 + a12) + 0.75f * a11;
    float he2 = 0.125f * (a20 + a22) + 0.75f * a21;
    float ho0 = 0.5f * (a01 + a02);
    float ho1 = 0.5f * (a11 + a12);
    float ho2 = 0.5f * (a21 + a22);
    ee = 0.125f * (he0 + he2) + 0.75f * he1;
    eo = 0.125f * (ho0 + ho2) + 0.75f * ho1;
    oe = 0.5f * (he1 + he2);
    oo = 0.5f * (ho1 + ho2);
}

// ---------------------------------------------------------------------------
// Fused mid levels (R13 vectorized version).
// ---------------------------------------------------------------------------
#define FNT 1024
#define SM_DN2 0
#define SM_HB3 14400
#define SM_DN3 21600
#define SM_DN4 25200
#define SM_DN5 26120
#define SM_F4  26360
#define SM_TOT 27280

__global__ void __launch_bounds__(FNT) fused_mid_kernel(
        const float* __restrict__ dn2,
        const float* __restrict__ colv, const float* __restrict__ rowv,
        const float* __restrict__ fixations,
        float* __restrict__ F2g) {
    extern __shared__ float sm[];
    float* s_dn2 = sm + SM_DN2;
    float* s_hb3 = sm + SM_HB3;
    float* s_F3  = sm + SM_HB3;
    float* s_dn3 = sm + SM_DN3;
    float* s_dn4 = sm + SM_DN4;
    float* s_dn5 = sm + SM_DN5;
    float* s_F4  = sm + SM_F4;

    const int p = blockIdx.x;
    const int b = p / 3;
    const int t = threadIdx.x;
    const float k0 = 0.0625f, k1 = 0.25f, k2 = 0.375f;

    const float4* src4 = (const float4*)(dn2 + (size_t)p * (H2 * W2));
    for (int i = t; i < (H2 * W2) / 4; i += FNT) ((float4*)s_dn2)[i] = src4[i];
    __syncthreads();

    // hb3 (90 x 80)
    for (int idx = t; idx < H2 * W3; idx += FNT) {
        int y = idx / W3;
        int ox = idx - y * W3;
        const float* row = s_dn2 + y * W2;
        int xc = 2 * ox;
        float v;
        if (ox >= 1 && ox <= W3 - 2) {
            float2 m = *(const float2*)(row + xc - 2);
            float2 n = *(const float2*)(row + xc);
            v = k0 * (m.x + row[xc + 2]) + k1 * (m.y + n.y) + k2 * n.x;
        } else {
            v = k2 * row[xc]
              + k1 * (row[refl(xc - 1, W2)] + row[refl(xc + 1, W2)])
              + k0 * (row[refl(xc - 2, W2)] + row[refl(xc + 2, W2)]);
        }
        s_hb3[idx] = v;
    }
    __syncthreads();

    // dn3 (45 x 80): paired columns
    for (int idx = t; idx < H3 * (W3 / 2); idx += FNT) {
        int oy = idx / (W3 / 2);
        int oxp = idx - oy * (W3 / 2);
        int yc = 2 * oy;
        int r0, r1, r3, r4;
        if (oy >= 1 && oy <= H3 - 2) {
            r0 = yc - 2; r1 = yc - 1; r3 = yc + 1; r4 = yc + 2;
        } else {
            r0 = refl(yc - 2, H2); r1 = refl(yc - 1, H2);
            r3 = refl(yc + 1, H2); r4 = refl(yc + 2, H2);
        }
        int col = 2 * oxp;
        float2 h0 = *(const float2*)&s_hb3[r0 * W3 + col];
        float2 h1 = *(const float2*)&s_hb3[r1 * W3 + col];
        float2 h2 = *(const float2*)&s_hb3[yc * W3 + col];
        float2 h3 = *(const float2*)&s_hb3[r3 * W3 + col];
        float2 h4 = *(const float2*)&s_hb3[r4 * W3 + col];
        float2 v;
        v.x = k0 * (h0.x + h4.x) + k1 * (h1.x + h3.x) + k2 * h2.x;
        v.y = k0 * (h0.y + h4.y) + k1 * (h1.y + h3.y) + k2 * h2.y;
        *(float2*)&s_dn3[oy * W3 + col] = v;
    }
    __syncthreads();

    for (int idx = t; idx < H4 * W4; idx += FNT)
        s_dn4[idx] = pd2_at(s_dn3, H3, W3, idx / W4, idx % W4);
    __syncthreads();
    for (int idx = t; idx < H5 * W5; idx += FNT)
        s_dn5[idx] = pd2_at(s_dn4, H4, W4, idx / W5, idx % W5);
    __syncthreads();

    const float fxx = fixations[2 * b];
    const float fyy = fixations[2 * b + 1];

    {   // level 4
        int x1 = min(max((int)(40.0f - fxx * 0.0625f), 0), W3 - W4);
        int y1 = min(max((int)(22.5f - fyy * 0.0625f), 0), H3 - H4);
        const float* cv = colv + CO4 + y1;
        const float* rv = rowv + RO4 + x1;
        const int qH = (H4 + 1) / 2, qW = W4 / 2;
        for (int idx = t; idx < qH * qW; idx += FNT) {
            int qy = idx / qW;
            int qx = idx - qy * qW;
            float ee, eo, oe, oo;
            pyrup_quad(s_dn5, H5, W5, qy, qx, ee, eo, oe, oo);
            int y0 = 2 * qy, x0 = 2 * qx;
            float rw0 = rv[x0], rw1 = rv[x0 + 1];
            float cw0 = cv[y0];
            s_F4[y0 * W4 + x0]     = ee + (s_dn4[y0 * W4 + x0]     - ee) * (cw0 * rw0);
            s_F4[y0 * W4 + x0 + 1] = eo + (s_dn4[y0 * W4 + x0 + 1] - eo) * (cw0 * rw1);
            if (y0 + 1 < H4) {
                float cw1 = cv[y0 + 1];
                s_F4[(y0 + 1) * W4 + x0]     = oe + (s_dn4[(y0 + 1) * W4 + x0]     - oe) * (cw1 * rw0);
                s_F4[(y0 + 1) * W4 + x0 + 1] = oo + (s_dn4[(y0 + 1) * W4 + x0 + 1] - oo) * (cw1 * rw1);
            }
        }
    }
    __syncthreads();

    {   // level 3
        int x1 = min(max((int)(80.0f - fxx * 0.125f), 0), W2 - W3);
        int y1 = min(max((int)(45.0f - fyy * 0.125f), 0), H2 - H3);
        const float* cv = colv + CO3 + y1;
        const float* rv = rowv + RO3 + x1;
        const int qH = (H3 + 1) / 2, qW = W3 / 2;
        for (int idx = t; idx < qH * qW; idx += FNT) {
            int qy = idx / qW;
            int qx = idx - qy * qW;
            float Fee, Feo, Foe, Foo, Dee, Deo, Doe, Doo;
            pyrup_quad(s_F4, H4, W4, qy, qx, Fee, Feo, Foe, Foo);
            pyrup_quad(s_dn4, H4, W4, qy, qx, Dee, Deo, Doe, Doo);
            int y0 = 2 * qy, x0 = 2 * qx;
            float rw0 = rv[x0], rw1 = rv[x0 + 1];
            float cw0 = cv[y0];
            s_F3[y0 * W3 + x0]     = Fee + (s_dn3[y0 * W3 + x0]     - Dee) * (cw0 * rw0);
            s_F3[y0 * W3 + x0 + 1] = Feo + (s_dn3[y0 * W3 + x0 + 1] - Deo) * (cw0 * rw1);
            if (y0 + 1 < H3) {
                float cw1 = cv[y0 + 1];
                s_F3[(y0 + 1) * W3 + x0]     = Foe + (s_dn3[(y0 + 1) * W3 + x0]     - Doe) * (cw1 * rw0);
                s_F3[(y0 + 1) * W3 + x0 + 1] = Foo + (s_dn3[(y0 + 1) * W3 + x0 + 1] - Doo) * (cw1 * rw1);
            }
        }
    }
    __syncthreads();

    {   // level 2 -> global F2
        int x1 = min(max((int)(160.0f - fxx * 0.25f), 0), W1 - W2);
        int y1 = min(max((int)(90.0f - fyy * 0.25f), 0), H1 - H2);
        const float* cv = colv + CO2 + y1;
        const float* rv = rowv + RO2 + x1;
        float* g = F2g + (size_t)p * (H2 * W2);
        const int qH = H2 / 2, qW = W2 / 2;
        for (int idx = t; idx < qH * qW; idx += FNT) {
            int qy = idx / qW;
            int qx = idx - qy * qW;
            float Fee, Feo, Foe, Foo, Dee, Deo, Doe, Doo;
            pyrup_quad(s_F3, H3, W3, qy, qx, Fee, Feo, Foe, Foo);
            pyrup_quad(s_dn3, H3, W3, qy, qx, Dee, Deo, Doe, Doo);
            int y0 = 2 * qy, x0 = 2 * qx;
            float rw0 = rv[x0], rw1 = rv[x0 + 1];
            float cw0 = cv[y0], cw1 = cv[y0 + 1];
            float2 o0, o1;
            o0.x = Fee + (s_dn2[y0 * W2 + x0]     - Dee) * (cw0 * rw0);
            o0.y = Feo + (s_dn2[y0 * W2 + x0 + 1] - Deo) * (cw0 * rw1);
            o1.x = Foe + (s_dn2[(y0 + 1) * W2 + x0]     - Doe) * (cw1 * rw0);
            o1.y = Foo + (s_dn2[(y0 + 1) * W2 + x0 + 1] - Doo) * (cw1 * rw1);
            *(float2*)(g + y0 * W2 + x0) = o0;
            *(float2*)(g + (y0 + 1) * W2 + x0) = o1;
        }
    }
}

// ---------------------------------------------------------------------------
// recon01 (R12 version): interior fast path, float2 staging, scalar epilogue.
// Block (16,16) -> 64x32 output pixels.
// ---------------------------------------------------------------------------
#define RQX 32
#define RQY 16

__global__ void __launch_bounds__(256) recon01(
        const float* __restrict__ F2,
        const float* __restrict__ dn2,
        const float* __restrict__ dn1,
        const float* __restrict__ images,
        const float* __restrict__ colv,
        const float* __restrict__ rowv,
        const float* __restrict__ fixations,
        float* __restrict__ out) {
    __shared__ float sD1[20][36];
    __shared__ float sF1[20][36];
    __shared__ float sF2[12][20];
    __shared__ float sD2[12][20];

    const int p = blockIdx.z;
    const int b = p / 3;
    const int qx0 = blockIdx.x * RQX;
    const int qy0 = blockIdx.y * RQY;
    const int tid = threadIdx.y * 16 + threadIdx.x;

    const float fxx = fixations[2 * b];
    const float fyy = fixations[2 * b + 1];
    const int x1_0 = min(max((int)(639.5f - fxx), 0), 1279 - W0);
    const int y1_0 = min(max((int)(359.5f - fyy), 0), 719 - H0);
    const int x1_1 = min(max((int)(320.0f - fxx * 0.5f), 0), W0 - W1);
    const int y1_1 = min(max((int)(180.0f - fyy * 0.5f), 0), H0 - H1);

    const int base1y = qy0 - 2, base1x = qx0 - 2;
    const int base2y = (qy0 >> 1) - 2, base2x = (qx0 >> 1) - 2;

    const bool interior = (qx0 >= 2) && (qx0 + 34 <= W1) && (qx0 / 2 + 18 <= W2)
                       && (qy0 >= 2) && (qy0 + 18 <= H1) && (qy0 / 2 + 10 <= H2);

    // ---- stage ---------------------------------------------------------------
    if (interior) {
        const float2* p1 = (const float2*)(dn1 + (size_t)p * (H1 * W1)
                                           + (size_t)base1y * W1 + base1x);
        const int st1 = W1 >> 1;
        for (int i = tid; i < 20 * 18; i += 256) {
            int r = i / 18;
            int j = i - r * 18;
            *(float2*)&sD1[r][2 * j] = p1[r * st1 + j];
        }
        const size_t off2 = (size_t)p * (H2 * W2) + (size_t)base2y * W2 + base2x;
        const float2* pf = (const float2*)(F2 + off2);
        const float2* pd = (const float2*)(dn2 + off2);
        const int st2 = W2 >> 1;
        for (int i = tid; i < 12 * 10; i += 256) {
            int r = i / 10;
            int j = i - r * 10;
            *(float2*)&sF2[r][2 * j] = pf[r * st2 + j];
            *(float2*)&sD2[r][2 * j] = pd[r * st2 + j];
        }
    } else {
        const float* s1 = dn1 + (size_t)p * (H1 * W1);
        for (int i = tid; i < 20 * 36; i += 256) {
            int r = i / 36;
            int c = i - r * 36;
            int gr = min(max(base1y + r, 0), H1 - 1);
            int gc = min(max(base1x + c, 0), W1 - 1);
            sD1[r][c] = s1[(size_t)gr * W1 + gc];
        }
        const float* sf = F2 + (size_t)p * (H2 * W2);
        const float* sd = dn2 + (size_t)p * (H2 * W2);
        for (int i = tid; i < 12 * 20; i += 256) {
            int r = i / 20;
            int c = i - r * 20;
            int gr = min(max(base2y + r, 0), H2 - 1);
            int gc = min(max(base2x + c, 0), W2 - 1);
            size_t off = (size_t)gr * W2 + gc;
            sF2[r][c] = sf[off];
            sD2[r][c] = sd[off];
        }
    }
    __syncthreads();

    // ---- F1 tile: 10x18 quads ------------------------------------------------
    {
        const float* cv1 = colv + CO1 + y1_1;
        const float* rv1 = rowv + RO1 + x1_1;
        const int Qy0 = (qy0 >> 1) - 1;
        const int Qx0 = (qx0 >> 1) - 1;
        if (interior) {
            for (int i = tid; i < 10 * 18; i += 256) {
                int qr = i / 18;
                int qc = i - qr * 18;
                float Fee, Feo, Foe, Foo, Dee, Deo, Doe, Doo;
                {
                    float a00 = sF2[qr][qc],     a01 = sF2[qr][qc + 1],     a02 = sF2[qr][qc + 2];
                    float a10 = sF2[qr + 1][qc], a11 = sF2[qr + 1][qc + 1], a12 = sF2[qr + 1][qc + 2];
                    float a20 = sF2[qr + 2][qc], a21 = sF2[qr + 2][qc + 1], a22 = sF2[qr + 2][qc + 2];
                    float he0 = 0.125f * (a00 + a02) + 0.75f * a01;
                    float he1 = 0.125f * (a10 + a12) + 0.75f * a11;
                    float he2 = 0.125f * (a20 + a22) + 0.75f * a21;
                    float ho0 = 0.5f * (a01 + a02);
                    float ho1 = 0.5f * (a11 + a12);
                    float ho2 = 0.5f * (a21 + a22);
                    Fee = 0.125f * (he0 + he2) + 0.75f * he1;
                    Feo = 0.125f * (ho0 + ho2) + 0.75f * ho1;
                    Foe = 0.5f * (he1 + he2);
                    Foo = 0.5f * (ho1 + ho2);
                }
                {
                    float a00 = sD2[qr][qc],     a01 = sD2[qr][qc + 1],     a02 = sD2[qr][qc + 2];
                    float a10 = sD2[qr + 1][qc], a11 = sD2[qr + 1][qc + 1], a12 = sD2[qr + 1][qc + 2];
                    float a20 = sD2[qr + 2][qc], a21 = sD2[qr + 2][qc + 1], a22 = sD2[qr + 2][qc + 2];
                    float he0 = 0.125f * (a00 + a02) + 0.75f * a01;
                    float he1 = 0.125f * (a10 + a12) + 0.75f * a11;
                    float he2 = 0.125f * (a20 + a22) + 0.75f * a21;
                    float ho0 = 0.5f * (a01 + a02);
                    float ho1 = 0.5f * (a11 + a12);
                    float ho2 = 0.5f * (a21 + a22);
                    Dee = 0.125f * (he0 + he2) + 0.75f * he1;
                    Deo = 0.125f * (ho0 + ho2) + 0.75f * ho1;
                    Doe = 0.5f * (he1 + he2);
                    Doo = 0.5f * (ho1 + ho2);
                }
                int gy = 2 * (Qy0 + qr), gx = 2 * (Qx0 + qc);
                int r0 = 2 * qr;
                int c0 = 2 * qc;
                float cw0 = cv1[gy], cw1 = cv1[gy + 1];
                float rw0 = rv1[gx], rw1 = rv1[gx + 1];
                float2 d0 = *(const float2*)&sD1[r0][c0];
                float2 d1 = *(const float2*)&sD1[r0 + 1][c0];
                float2 f0, f1;
                f0.x = Fee + (d0.x - Dee) * (cw0 * rw0);
                f0.y = Feo + (d0.y - Deo) * (cw0 * rw1);
                f1.x = Foe + (d1.x - Doe) * (cw1 * rw0);
                f1.y = Foo + (d1.y - Doo) * (cw1 * rw1);
                *(float2*)&sF1[r0][c0]     = f0;
                *(float2*)&sF1[r0 + 1][c0] = f1;
            }
        } else {
            for (int i = tid; i < 10 * 18; i += 256) {
                int qr = i / 18;
                int qc = i - qr * 18;
                int Qy = Qy0 + qr;
                int Qx = Qx0 + qc;
                if (Qy < 0 || Qy >= H2 || Qx < 0 || Qx >= W2) continue;

                int yu = ((Qy == 0) ? 1 : Qy - 1) - base2y;
                int yc = Qy - base2y;
                int yd = ((Qy < H2 - 1) ? Qy + 1 : H2 - 1) - base2y;
                int xl = ((Qx == 0) ? 1 : Qx - 1) - base2x;
                int xc = Qx - base2x;
                int xr = ((Qx < W2 - 1) ? Qx + 1 : W2 - 1) - base2x;

                float Fee, Feo, Foe, Foo, Dee, Deo, Doe, Doo;
                {
                    float a00 = sF2[yu][xl], a01 = sF2[yu][xc], a02 = sF2[yu][xr];
                    float a10 = sF2[yc][xl], a11 = sF2[yc][xc], a12 = sF2[yc][xr];
                    float a20 = sF2[yd][xl], a21 = sF2[yd][xc], a22 = sF2[yd][xr];
                    float he0 = 0.125f * (a00 + a02) + 0.75f * a01;
                    float he1 = 0.125f * (a10 + a12) + 0.75f * a11;
                    float he2 = 0.125f * (a20 + a22) + 0.75f * a21;
                    float ho0 = 0.5f * (a01 + a02);
                    float ho1 = 0.5f * (a11 + a12);
                    float ho2 = 0.5f * (a21 + a22);
                    Fee = 0.125f * (he0 + he2) + 0.75f * he1;
                    Feo = 0.125f * (ho0 + ho2) + 0.75f * ho1;
                    Foe = 0.5f * (he1 + he2);
                    Foo = 0.5f * (ho1 + ho2);
                }
                {
                    float a00 = sD2[yu][xl], a01 = sD2[yu][xc], a02 = sD2[yu][xr];
                    float a10 = sD2[yc][xl], a11 = sD2[yc][xc], a12 = sD2[yc][xr];
                    float a20 = sD2[yd][xl], a21 = sD2[yd][xc], a22 = sD2[yd][xr];
                    float he0 = 0.125f * (a00 + a02) + 0.75f * a01;
                    float he1 = 0.125f * (a10 + a12) + 0.75f * a11;
                    float he2 = 0.125f * (a20 + a22) + 0.75f * a21;
                    float ho0 = 0.5f * (a01 + a02);
                    float ho1 = 0.5f * (a11 + a12);
                    float ho2 = 0.5f * (a21 + a22);
                    Dee = 0.125f * (he0 + he2) + 0.75f * he1;
                    Deo = 0.125f * (ho0 + ho2) + 0.75f * ho1;
                    Doe = 0.5f * (he1 + he2);
                    Doo = 0.5f * (ho1 + ho2);
                }

                int gy = 2 * Qy, gx = 2 * Qx;
                int r0 = gy - base1y;
                int c0 = gx - base1x;
                float cw0 = cv1[gy], cw1 = cv1[gy + 1];
                float rw0 = rv1[gx], rw1 = rv1[gx + 1];
                sF1[r0][c0]         = Fee + (sD1[r0][c0]         - Dee) * (cw0 * rw0);
                sF1[r0][c0 + 1]     = Feo + (sD1[r0][c0 + 1]     - Deo) * (cw0 * rw1);
                sF1[r0 + 1][c0]     = Foe + (sD1[r0 + 1][c0]     - Doe) * (cw1 * rw0);
                sF1[r0 + 1][c0 + 1] = Foo + (sD1[r0 + 1][c0 + 1] - Doo) * (cw1 * rw1);
            }
        }
    }
    __syncthreads();

    // ---- level-0 recon: two quads per thread, float4 rows -------------------
    const int ty = threadIdx.y;
    const int qy = qy0 + ty;
    if (qy >= H1) return;
    const int qxA = qx0 + 2 * threadIdx.x;

    const int cb = 2 * threadIdx.x + 2;
    int la, rb, ru, rd;
    if (interior) {
        la = cb - 1;
        rb = cb + 2;
        ru = ty + 1;
        rd = ty + 3;
    } else {
        la = (qxA == 0) ? 3 : cb - 1;
        rb = (qxA + 1 < W1 - 1) ? cb + 2 : (W1 + 1 - qx0);
        ru = (qy == 0) ? 3 : ty + 1;
        rd = (qy < H1 - 1) ? ty + 3 : ty + 2;
    }
    const int rc = ty + 2;

    float FheA[3], FhoA[3], FheB[3], FhoB[3];
    float DheA[3], DhoA[3], DheB[3], DhoB[3];
    int rows[3] = {ru, rc, rd};
#pragma unroll
    for (int i = 0; i < 3; i++) {
        int r = rows[i];
        {
            float vl = sF1[r][la], v0 = sF1[r][cb], v1 = sF1[r][cb + 1], vr = sF1[r][rb];
            FheA[i] = 0.125f * (vl + v1) + 0.75f * v0;
            FhoA[i] = 0.5f * (v0 + v1);
            FheB[i] = 0.125f * (v0 + vr) + 0.75f * v1;
            FhoB[i] = 0.5f * (v1 + vr);
        }
        {
            float vl = sD1[r][la], v0 = sD1[r][cb], v1 = sD1[r][cb + 1], vr = sD1[r][rb];
            DheA[i] = 0.125f * (vl + v1) + 0.75f * v0;
            DhoA[i] = 0.5f * (v0 + v1);
            DheB[i] = 0.125f * (v0 + vr) + 0.75f * v1;
            DhoB[i] = 0.5f * (v1 + vr);
        }
    }

    const int x0 = 2 * qxA;
    const int y0 = 2 * qy;
    const size_t obase = (size_t)p * (H0 * W0);
    const float* rv = rowv + RO0 + x1_0 + x0;
    float rw0 = rv[0], rw1 = rv[1], rw2 = rv[2], rw3 = rv[3];
    float cw0 = colv[CO0 + y0 + y1_0], cw1 = colv[CO0 + y0 + 1 + y1_0];

    {
        float uF0 = 0.125f * (FheA[0] + FheA[2]) + 0.75f * FheA[1];
        float uF1 = 0.125f * (FhoA[0] + FhoA[2]) + 0.75f * FhoA[1];
        float uF2 = 0.125f * (FheB[0] + FheB[2]) + 0.75f * FheB[1];
        float uF3 = 0.125f * (FhoB[0] + FhoB[2]) + 0.75f * FhoB[1];
        float uD0 = 0.125f * (DheA[0] + DheA[2]) + 0.75f * DheA[1];
        float uD1 = 0.125f * (DhoA[0] + DhoA[2]) + 0.75f * DhoA[1];
        float uD2 = 0.125f * (DheB[0] + DheB[2]) + 0.75f * DheB[1];
        float uD3 = 0.125f * (DhoB[0] + DhoB[2]) + 0.75f * DhoB[1];
        const float4 dc = *(const float4*)(images + obase + (size_t)y0 * W0 + x0);
        float4 o;
        o.x = uF0 + (dc.x - uD0) * (cw0 * rw0);
        o.y = uF1 + (dc.y - uD1) * (cw0 * rw1);
        o.z = uF2 + (dc.z - uD2) * (cw0 * rw2);
        o.w = uF3 + (dc.w - uD3) * (cw0 * rw3);
        *(float4*)(out + obase + (size_t)y0 * W0 + x0) = o;
    }
    {
        float uF0 = 0.5f * (FheA[1] + FheA[2]);
        float uF1 = 0.5f * (FhoA[1] + FhoA[2]);
        float uF2 = 0.5f * (FheB[1] + FheB[2]);
        float uF3 = 0.5f * (FhoB[1] + FhoB[2]);
        float uD0 = 0.5f * (DheA[1] + DheA[2]);
        float uD1 = 0.5f * (DhoA[1] + DhoA[2]);
        float uD2 = 0.5f * (DheB[1] + DheB[2]);
        float uD3 = 0.5f * (DhoB[1] + DhoB[2]);
        const float4 dc = *(const float4*)(images + obase + (size_t)(y0 + 1) * W0 + x0);
        float4 o;
        o.x = uF0 + (dc.x - uD0) * (cw1 * rw0);
        o.y = uF1 + (dc.y - uD1) * (cw1 * rw1);
        o.z = uF2 + (dc.z - uD2) * (cw1 * rw2);
        o.w = uF3 + (dc.w - uD3) * (cw1 * rw3);
        *(float4*)(out + obase + (size_t)(y0 + 1) * W0 + x0) = o;
    }
}

// ---------------------------------------------------------------------------

static inline int idiv(int a, int b) { return (a + b - 1) / b; }

extern "C" void kernel_launch(void* const* d_in, const int* in_sizes, int n_in,
                              void* d_out, int out_size) {
    (void)in_sizes; (void)n_in; (void)out_size;
    const float* images = (const float*)d_in[0];
    const float* fix    = (const float*)d_in[1];
    float* out = (float*)d_out;

    float *rowv, *colv, *dn1, *dn2, *F2;
    cudaGetSymbolAddress((void**)&rowv, g_rowv);
    cudaGetSymbolAddress((void**)&colv, g_colv);
    cudaGetSymbolAddress((void**)&dn1, g_dn1);
    cudaGetSymbolAddress((void**)&dn2, g_dn2);
    cudaGetSymbolAddress((void**)&F2, g_F2);

    cudaFuncSetAttribute(fused_mid_kernel,
                         cudaFuncAttributeMaxDynamicSharedMemorySize,
                         SM_TOT * (int)sizeof(float));

    {
        dim3 blk(16, 16);
        // pyrdown1 + filter generation (extra z slice)
        dim3 g1(idiv(W1, PTX), idiv(H1, PTY), NPL + 1);
        pyrdown_st<<<g1, blk>>>(images, dn1, H0, W0, H1, W1, rowv, colv, NPL);
        dim3 g2(idiv(W2, PTX), idiv(H2, PTY), NPL);
        pyrdown_st<<<g2, blk>>>(dn1, dn2, H1, W1, H2, W2, rowv, colv, NPL);
    }

    fused_mid_kernel<<<NPL, FNT, SM_TOT * (int)sizeof(float)>>>(
        dn2, colv, rowv, fix, F2);

    {
        dim3 blk(16, 16);
        dim3 g0((W0 / 2) / RQX, idiv(H0 / 2, RQY), NPL);
        recon01<<<g0, blk>>>(F2, dn2, dn1, images, colv, rowv, fix, out);
    }
}